// round 7
// baseline (speedup 1.0000x reference)
#include <cuda_runtime.h>
#include <cuda_bf16.h>
#include <cstdint>

#define N 8192
#define D 512

static __device__ float g_dist[(size_t)N * N];   // 256 MB scratch
static __device__ float g_sqn[N];
static __device__ __nv_bfloat16 g_hi[(size_t)N * D];
static __device__ __nv_bfloat16 g_lo[(size_t)N * D];

// ---------------------------------------------------------------------------
// helpers
// ---------------------------------------------------------------------------
__device__ __forceinline__ uint32_t smem_u32(const void* p) {
    uint32_t a;
    asm("{ .reg .u64 t; cvta.to.shared.u64 t, %1; cvt.u32.u64 %0, t; }" : "=r"(a) : "l"(p));
    return a;
}
__device__ __forceinline__ uint32_t sw128(uint32_t b) { return b ^ ((b >> 3) & 0x70); }

__device__ __forceinline__ void cp16(uint32_t dst, const void* src) {
    asm volatile("cp.async.cg.shared.global [%0], [%1], 16;" :: "r"(dst), "l"(src));
}
#define CP_COMMIT() asm volatile("cp.async.commit_group;" ::: "memory")
#define CP_WAIT0()  asm volatile("cp.async.wait_group 0;" ::: "memory")
#define CP_WAIT1()  asm volatile("cp.async.wait_group 1;" ::: "memory")

__device__ __forceinline__ void ldsm_x4(uint32_t* r, uint32_t addr) {
    asm volatile("ldmatrix.sync.aligned.m8n8.x4.shared.b16 {%0,%1,%2,%3}, [%4];"
                 : "=r"(r[0]), "=r"(r[1]), "=r"(r[2]), "=r"(r[3]) : "r"(addr));
}
__device__ __forceinline__ void mma16816(float* d, const uint32_t* a, uint32_t b0, uint32_t b1) {
    asm volatile(
        "mma.sync.aligned.m16n8k16.row.col.f32.bf16.bf16.f32 "
        "{%0,%1,%2,%3}, {%4,%5,%6,%7}, {%8,%9}, {%0,%1,%2,%3};"
        : "+f"(d[0]), "+f"(d[1]), "+f"(d[2]), "+f"(d[3])
        : "r"(a[0]), "r"(a[1]), "r"(a[2]), "r"(a[3]), "r"(b0), "r"(b1));
}

// ---------------------------------------------------------------------------
// Kernel 1: sqnorms + fp32 -> bf16 hi/lo split (one warp per row), zero out
// ---------------------------------------------------------------------------
__global__ void prep_kernel(const float* __restrict__ emb, float* __restrict__ out) {
    if (blockIdx.x == 0 && threadIdx.x == 0) *out = 0.0f;
    int gw   = (blockIdx.x * blockDim.x + threadIdx.x) >> 5;
    int lane = threadIdx.x & 31;
    if (gw >= N) return;
    const float4* src = (const float4*)(emb + (size_t)gw * D);
    float s = 0.0f;
#pragma unroll
    for (int q = 0; q < 4; q++) {
        float4 v = src[lane + q * 32];
        s = fmaf(v.x, v.x, fmaf(v.y, v.y, fmaf(v.z, v.z, fmaf(v.w, v.w, s))));
        __nv_bfloat16 h[4], l[4];
        float f[4] = {v.x, v.y, v.z, v.w};
#pragma unroll
        for (int u = 0; u < 4; u++) {
            h[u] = __float2bfloat16(f[u]);
            l[u] = __float2bfloat16(f[u] - __bfloat162float(h[u]));
        }
        size_t off = (size_t)gw * D + lane * 4 + q * 128;
        *(uint2*)(g_hi + off) = *(const uint2*)h;
        *(uint2*)(g_lo + off) = *(const uint2*)l;
    }
#pragma unroll
    for (int o = 16; o > 0; o >>= 1) s += __shfl_down_sync(0xffffffffu, s, o);
    if (lane == 0) g_sqn[gw] = s;
}

// ---------------------------------------------------------------------------
// Kernel 2: 128x256-tile symmetric distance GEMM via mma.sync bf16-split.
// Tiles (bi, bj2) kept iff bj2 >= bi/2 (1056 CTAs); warp tile 64x64.
// 3-stage cp.async pipeline; mirror writes via smem transpose.
// ---------------------------------------------------------------------------
#define STAGE_BYTES 49152          // A 16KB + B 32KB per K=64 chunk
#define NSTAGE 3
#define SSTW 260                   // smem transpose row stride (floats)
#define GEMM_SMEM (NSTAGE * STAGE_BYTES)   // 147456 >= 128*SSTW*4 = 133120
#define NCHUNK 24                  // 3 passes x 8 chunks

__device__ __forceinline__ void load_chunk(int c, uint32_t st, int i0, int j0, int tid) {
    const int pass = c >> 3, kc = c & 7;
    const __nv_bfloat16* Asrc = (pass == 2) ? g_lo : g_hi;
    const __nv_bfloat16* Bsrc = (pass == 1) ? g_lo : g_hi;
#pragma unroll
    for (int q = 0; q < 4; q++) {               // A: 128 rows x 8 segs
        int idx = q * 256 + tid;
        int row = idx >> 3, seg = idx & 7;
        cp16(st + sw128(row * 128 + seg * 16),
             Asrc + (size_t)(i0 + row) * D + kc * 64 + seg * 8);
    }
#pragma unroll
    for (int q = 0; q < 8; q++) {               // B: 256 rows x 8 segs
        int idx = q * 256 + tid;
        int row = idx >> 3, seg = idx & 7;
        cp16(st + 16384 + sw128(row * 128 + seg * 16),
             Bsrc + (size_t)(j0 + row) * D + kc * 64 + seg * 8);
    }
    CP_COMMIT();
}

__global__ __launch_bounds__(256, 1) void gemm_kernel() {
    extern __shared__ __align__(1024) uint8_t dsm[];
    const int tid  = threadIdx.x;
    const int wid  = tid >> 5;
    const int lane = tid & 31;

    // tile decode: for bi in [0,64), bj2 in [bi/2, 32)
    int t = blockIdx.x, bi = 0;
    for (;;) { int cnt = 32 - (bi >> 1); if (t < cnt) break; t -= cnt; bi++; }
    const int bj2 = (bi >> 1) + t;
    const int i0 = bi * 128, j0 = bj2 * 256;

    const uint32_t dsm_b = smem_u32(dsm);
    const int wm = (wid >> 2) * 64;   // warp m-offset (0/64)
    const int wn = (wid & 3) * 64;    // warp n-offset (0/64/128/192)

    float acc[4][8][4];
#pragma unroll
    for (int a = 0; a < 4; a++)
#pragma unroll
        for (int b = 0; b < 8; b++)
#pragma unroll
            for (int k = 0; k < 4; k++) acc[a][b][k] = 0.0f;

    load_chunk(0, dsm_b, i0, j0, tid);
    load_chunk(1, dsm_b + STAGE_BYTES, i0, j0, tid);

    const uint32_t lrow = lane & 15, lhalf = (lane >> 4) * 16;
    int slot = 0;
    for (int c = 0; c < NCHUNK; c++) {
        if (c + 1 < NCHUNK) CP_WAIT1(); else CP_WAIT0();
        __syncthreads();
        if (c + 2 < NCHUNK) {
            int ns = slot + 2; if (ns >= NSTAGE) ns -= NSTAGE;
            load_chunk(c + 2, dsm_b + ns * STAGE_BYTES, i0, j0, tid);
        }
        const uint32_t stA = dsm_b + slot * STAGE_BYTES;
        const uint32_t stB = stA + 16384;
#pragma unroll
        for (int kk = 0; kk < 4; kk++) {
            uint32_t afr[4][4], bfr[4][4];
#pragma unroll
            for (int mf = 0; mf < 4; mf++)
                ldsm_x4(afr[mf], stA + sw128((wm + mf * 16 + lrow) * 128 + kk * 32 + lhalf));
#pragma unroll
            for (int g = 0; g < 4; g++)
                ldsm_x4(bfr[g], stB + sw128((wn + g * 16 + lrow) * 128 + kk * 32 + lhalf));
#pragma unroll
            for (int mf = 0; mf < 4; mf++)
#pragma unroll
                for (int nf = 0; nf < 8; nf++)
                    mma16816(acc[mf][nf], afr[mf],
                             bfr[nf >> 1][nf & 1], bfr[nf >> 1][(nf & 1) + 2]);
        }
        if (++slot == NSTAGE) slot = 0;
    }
    __syncthreads();   // all reads done before smem reuse

    // ---- epilogue: distances into smem transpose buffer
    float* smemf = (float*)dsm;
    const int qr = lane >> 2, qc = (lane & 3) * 2;
#pragma unroll
    for (int mf = 0; mf < 4; mf++) {
        const int r0 = wm + mf * 16 + qr;
        const float si0 = g_sqn[i0 + r0], si1 = g_sqn[i0 + r0 + 8];
#pragma unroll
        for (int nf = 0; nf < 8; nf++) {
            const int c0 = wn + nf * 8 + qc;
            const float sj0 = g_sqn[j0 + c0], sj1 = g_sqn[j0 + c0 + 1];
            const float* p = acc[mf][nf];
            float v00 = si0 + sj0 - 2.0f * p[0];
            float v01 = si0 + sj1 - 2.0f * p[1];
            float v10 = si1 + sj0 - 2.0f * p[2];
            float v11 = si1 + sj1 - 2.0f * p[3];
            if (i0 + r0     == j0 + c0)     v00 += 10000000000.0f;
            if (i0 + r0     == j0 + c0 + 1) v01 += 10000000000.0f;
            if (i0 + r0 + 8 == j0 + c0)     v10 += 10000000000.0f;
            if (i0 + r0 + 8 == j0 + c0 + 1) v11 += 10000000000.0f;
            smemf[r0 * SSTW + c0]           = v00;
            smemf[r0 * SSTW + c0 + 1]       = v01;
            smemf[(r0 + 8) * SSTW + c0]     = v10;
            smemf[(r0 + 8) * SSTW + c0 + 1] = v11;
        }
    }
    __syncthreads();

    {   // direct write: 2 threads per row, 128 cols each
        const int row = tid >> 1, seg = tid & 1;
        const float* sr = smemf + row * SSTW + seg * 128;
        float4* dst = (float4*)(g_dist + (size_t)(i0 + row) * N + j0 + seg * 128);
#pragma unroll
        for (int u = 0; u < 32; u++) dst[u] = *(const float4*)(sr + u * 4);
    }
    {   // mirror write: 1 thread per column j (256), gather smem column
        const int c = tid;
        float* dst = g_dist + (size_t)(j0 + c) * N + i0;
#pragma unroll
        for (int u = 0; u < 32; u++) {
            float4 v;
            v.x = smemf[(u * 4 + 0) * SSTW + c];
            v.y = smemf[(u * 4 + 1) * SSTW + c];
            v.z = smemf[(u * 4 + 2) * SSTW + c];
            v.w = smemf[(u * 4 + 3) * SSTW + c];
            *(float4*)(dst + u * 4) = v;
        }
    }
}

// ---------------------------------------------------------------------------
// Kernel 3: warp-per-row top-15 + softmax*mask weights + batch entropy.
// ---------------------------------------------------------------------------
__device__ __forceinline__ void ins15(float loc[15], float v) {
    if (v < loc[14]) {
        loc[14] = v;
#pragma unroll
        for (int q = 14; q > 0; q--) {
            if (loc[q] < loc[q - 1]) { float tt = loc[q - 1]; loc[q - 1] = loc[q]; loc[q] = tt; }
        }
    }
}

__global__ __launch_bounds__(256) void row_kernel(const int* __restrict__ labels,
                                                  float* __restrict__ out) {
    const int tid  = threadIdx.x;
    const int wid  = tid >> 5;
    const int lane = tid & 31;
    const int row  = blockIdx.x * 8 + wid;

    __shared__ float bsum;
    if (tid == 0) bsum = 0.0f;
    __syncthreads();

    const float4* dr4 = (const float4*)(g_dist + (size_t)row * N);
    const int4*   lb4 = (const int4*)labels;
    const float INF = __int_as_float(0x7f800000);

    float loc[15];
#pragma unroll
    for (int q = 0; q < 15; q++) loc[q] = INF;
#pragma unroll 4
    for (int k = 0; k < 64; k++) {
        float4 v = dr4[lane + k * 32];
        ins15(loc, v.x); ins15(loc, v.y); ins15(loc, v.z); ins15(loc, v.w);
    }

    float dmin = 0.0f, kth = 0.0f;
#pragma unroll
    for (int r = 0; r < 15; r++) {
        float h = loc[0];
        float m = h;
#pragma unroll
        for (int o = 16; o > 0; o >>= 1) m = fminf(m, __shfl_xor_sync(0xffffffffu, m, o));
        unsigned ball = __ballot_sync(0xffffffffu, h == m);
        int winner = __ffs(ball) - 1;
        if (lane == winner) {
#pragma unroll
            for (int q = 0; q < 14; q++) loc[q] = loc[q + 1];
            loc[14] = INF;
        }
        if (r == 0)  dmin = m;
        if (r == 14) kth  = m;
    }

    float Z = 0.f, S = 0.f, s0 = 0.f, s1 = 0.f, s2 = 0.f;
#pragma unroll 2
    for (int k = 0; k < 64; k++) {
        float4 dv = dr4[lane + k * 32];
        int4   lb = lb4[lane + k * 32];
        float d, e, km, tt;
        d = dv.x; e = __expf(dmin - d); km = 1.0f / (1.0f + __expf(d - kth)); tt = e * km;
        Z += e; S += tt;
        s0 += (lb.x == 0) ? tt : 0.f; s1 += (lb.x == 1) ? tt : 0.f; s2 += (lb.x == 2) ? tt : 0.f;
        d = dv.y; e = __expf(dmin - d); km = 1.0f / (1.0f + __expf(d - kth)); tt = e * km;
        Z += e; S += tt;
        s0 += (lb.y == 0) ? tt : 0.f; s1 += (lb.y == 1) ? tt : 0.f; s2 += (lb.y == 2) ? tt : 0.f;
        d = dv.z; e = __expf(dmin - d); km = 1.0f / (1.0f + __expf(d - kth)); tt = e * km;
        Z += e; S += tt;
        s0 += (lb.z == 0) ? tt : 0.f; s1 += (lb.z == 1) ? tt : 0.f; s2 += (lb.z == 2) ? tt : 0.f;
        d = dv.w; e = __expf(dmin - d); km = 1.0f / (1.0f + __expf(d - kth)); tt = e * km;
        Z += e; S += tt;
        s0 += (lb.w == 0) ? tt : 0.f; s1 += (lb.w == 1) ? tt : 0.f; s2 += (lb.w == 2) ? tt : 0.f;
    }
#pragma unroll
    for (int o = 16; o > 0; o >>= 1) {
        Z  += __shfl_down_sync(0xffffffffu, Z,  o);
        S  += __shfl_down_sync(0xffffffffu, S,  o);
        s0 += __shfl_down_sync(0xffffffffu, s0, o);
        s1 += __shfl_down_sync(0xffffffffu, s1, o);
        s2 += __shfl_down_sync(0xffffffffu, s2, o);
    }
    if (lane == 0) {
        float denom = S + 1e-8f * Z;
        float p0 = s0 / denom, p1 = s1 / denom, p2 = s2 / denom;
        float H = -(p0 * logf(p0 + 1e-8f) + p1 * logf(p1 + 1e-8f) + p2 * logf(p2 + 1e-8f));
        float nH = H / (logf(3.0f) + 1e-8f);
        atomicAdd(&bsum, -nH * (1.0f / N));
    }
    __syncthreads();
    if (tid == 0) atomicAdd(out, bsum);
}

// ---------------------------------------------------------------------------
extern "C" void kernel_launch(void* const* d_in, const int* in_sizes, int n_in,
                              void* d_out, int out_size) {
    const float* emb    = (const float*)d_in[0];
    const int*   labels = (const int*)d_in[1];
    float*       out    = (float*)d_out;

    cudaFuncSetAttribute(gemm_kernel, cudaFuncAttributeMaxDynamicSharedMemorySize, GEMM_SMEM);

    prep_kernel<<<N / 8, 256>>>(emb, out);
    gemm_kernel<<<1056, 256, GEMM_SMEM>>>();   // 128x256 tiles, bj2 >= bi/2
    row_kernel<<<N / 8, 256>>>(labels, out);
}

// round 9
// speedup vs baseline: 1.2397x; 1.2397x over previous
#include <cuda_runtime.h>
#include <cuda_bf16.h>
#include <cstdint>

#define N 8192
#define D 512

static __device__ float g_dist[(size_t)N * N];   // 256 MB scratch
static __device__ float g_sqn[N];
static __device__ __nv_bfloat16 g_hi[(size_t)N * D];
static __device__ __nv_bfloat16 g_lo[(size_t)N * D];

// ---------------------------------------------------------------------------
// helpers
// ---------------------------------------------------------------------------
__device__ __forceinline__ uint32_t smem_u32(const void* p) {
    uint32_t a;
    asm("{ .reg .u64 t; cvta.to.shared.u64 t, %1; cvt.u32.u64 %0, t; }" : "=r"(a) : "l"(p));
    return a;
}
__device__ __forceinline__ uint32_t sw128(uint32_t b) { return b ^ ((b >> 3) & 0x70); }

__device__ __forceinline__ void cp16(uint32_t dst, const void* src) {
    asm volatile("cp.async.cg.shared.global [%0], [%1], 16;" :: "r"(dst), "l"(src));
}
#define CP_COMMIT() asm volatile("cp.async.commit_group;" ::: "memory")
#define CP_WAIT0()  asm volatile("cp.async.wait_group 0;" ::: "memory")
#define CP_WAIT1()  asm volatile("cp.async.wait_group 1;" ::: "memory")

__device__ __forceinline__ void ldsm_x4(uint32_t* r, uint32_t addr) {
    asm volatile("ldmatrix.sync.aligned.m8n8.x4.shared.b16 {%0,%1,%2,%3}, [%4];"
                 : "=r"(r[0]), "=r"(r[1]), "=r"(r[2]), "=r"(r[3]) : "r"(addr));
}
__device__ __forceinline__ void mma16816(float* d, const uint32_t* a, uint32_t b0, uint32_t b1) {
    asm volatile(
        "mma.sync.aligned.m16n8k16.row.col.f32.bf16.bf16.f32 "
        "{%0,%1,%2,%3}, {%4,%5,%6,%7}, {%8,%9}, {%0,%1,%2,%3};"
        : "+f"(d[0]), "+f"(d[1]), "+f"(d[2]), "+f"(d[3])
        : "r"(a[0]), "r"(a[1]), "r"(a[2]), "r"(a[3]), "r"(b0), "r"(b1));
}

// ---------------------------------------------------------------------------
// Kernel 1: sqnorms + fp32 -> bf16 hi/lo split (one warp per row), zero out
// ---------------------------------------------------------------------------
__global__ void prep_kernel(const float* __restrict__ emb, float* __restrict__ out) {
    if (blockIdx.x == 0 && threadIdx.x == 0) *out = 0.0f;
    int gw   = (blockIdx.x * blockDim.x + threadIdx.x) >> 5;
    int lane = threadIdx.x & 31;
    if (gw >= N) return;
    const float4* src = (const float4*)(emb + (size_t)gw * D);
    float s = 0.0f;
#pragma unroll
    for (int q = 0; q < 4; q++) {
        float4 v = src[lane + q * 32];
        s = fmaf(v.x, v.x, fmaf(v.y, v.y, fmaf(v.z, v.z, fmaf(v.w, v.w, s))));
        __nv_bfloat16 h[4], l[4];
        float f[4] = {v.x, v.y, v.z, v.w};
#pragma unroll
        for (int u = 0; u < 4; u++) {
            h[u] = __float2bfloat16(f[u]);
            l[u] = __float2bfloat16(f[u] - __bfloat162float(h[u]));
        }
        size_t off = (size_t)gw * D + lane * 4 + q * 128;
        *(uint2*)(g_hi + off) = *(const uint2*)h;
        *(uint2*)(g_lo + off) = *(const uint2*)l;
    }
#pragma unroll
    for (int o = 16; o > 0; o >>= 1) s += __shfl_down_sync(0xffffffffu, s, o);
    if (lane == 0) g_sqn[gw] = s;
}

// ---------------------------------------------------------------------------
// Kernel 2: 128x128-tile symmetric distance GEMM via mma.sync bf16-split.
// Upper-triangle tiles (2080 CTAs), 3-stage cp.async pipeline, mirror writes.
// (R6 configuration — measured best)
// ---------------------------------------------------------------------------
#define STAGE_BYTES 32768          // A 16KB + B 16KB per K=64 chunk
#define NSTAGE 3
#define SST 132                    // smem transpose row stride (floats)
#define GEMM_SMEM (NSTAGE * STAGE_BYTES)  // 98304 >= 128*SST*4 = 67584
#define NCHUNK 24                  // 3 passes x 8 chunks

__device__ __forceinline__ void load_chunk(int c, uint32_t st, int i0, int j0, int tid) {
    const int pass = c >> 3, kc = c & 7;
    const __nv_bfloat16* Asrc = (pass == 2) ? g_lo : g_hi;
    const __nv_bfloat16* Bsrc = (pass == 1) ? g_lo : g_hi;
#pragma unroll
    for (int q = 0; q < 4; q++) {
        int idx = q * 256 + tid;
        int row = idx >> 3, seg = idx & 7;
        cp16(st + sw128(row * 128 + seg * 16),
             Asrc + (size_t)(i0 + row) * D + kc * 64 + seg * 8);
    }
#pragma unroll
    for (int q = 0; q < 4; q++) {
        int idx = q * 256 + tid;
        int row = idx >> 3, seg = idx & 7;
        cp16(st + 16384 + sw128(row * 128 + seg * 16),
             Bsrc + (size_t)(j0 + row) * D + kc * 64 + seg * 8);
    }
    CP_COMMIT();
}

__global__ __launch_bounds__(256, 2) void gemm_kernel() {
    extern __shared__ __align__(1024) uint8_t dsm[];
    const int tid  = threadIdx.x;
    const int wid  = tid >> 5;
    const int lane = tid & 31;

    // upper-triangle tile decode (64x64 grid of 128-tiles)
    int t = blockIdx.x, bi = 0, rem = 64;
    while (t >= rem) { t -= rem; bi++; rem--; }
    const int bj = bi + t;
    const int i0 = bi * 128, j0 = bj * 128;

    const uint32_t dsm_b = smem_u32(dsm);
    const int wm = (wid >> 2) * 64;   // warp m-offset (0/64)
    const int wn = (wid & 3) * 32;    // warp n-offset (0/32/64/96)

    float acc[4][4][4];
#pragma unroll
    for (int a = 0; a < 4; a++)
#pragma unroll
        for (int b = 0; b < 4; b++)
#pragma unroll
            for (int k = 0; k < 4; k++) acc[a][b][k] = 0.0f;

    load_chunk(0, dsm_b, i0, j0, tid);
    load_chunk(1, dsm_b + STAGE_BYTES, i0, j0, tid);

    const uint32_t lrow = lane & 15, lhalf = (lane >> 4) * 16;
    int slot = 0;
    for (int c = 0; c < NCHUNK; c++) {
        if (c + 1 < NCHUNK) CP_WAIT1(); else CP_WAIT0();
        __syncthreads();
        if (c + 2 < NCHUNK) {
            int ns = slot + 2; if (ns >= NSTAGE) ns -= NSTAGE;
            load_chunk(c + 2, dsm_b + ns * STAGE_BYTES, i0, j0, tid);
        }
        const uint32_t stA = dsm_b + slot * STAGE_BYTES;
        const uint32_t stB = stA + 16384;
#pragma unroll
        for (int kk = 0; kk < 4; kk++) {
            uint32_t afr[4][4], bfr[2][4];
#pragma unroll
            for (int mf = 0; mf < 4; mf++)
                ldsm_x4(afr[mf], stA + sw128((wm + mf * 16 + lrow) * 128 + kk * 32 + lhalf));
#pragma unroll
            for (int g = 0; g < 2; g++)
                ldsm_x4(bfr[g], stB + sw128((wn + g * 16 + lrow) * 128 + kk * 32 + lhalf));
#pragma unroll
            for (int mf = 0; mf < 4; mf++)
#pragma unroll
                for (int nf = 0; nf < 4; nf++)
                    mma16816(acc[mf][nf], afr[mf],
                             bfr[nf >> 1][nf & 1], bfr[nf >> 1][(nf & 1) + 2]);
        }
        if (++slot == NSTAGE) slot = 0;
    }
    __syncthreads();   // everyone done reading stages before smem reuse

    // ---- epilogue: distances into smem transpose buffer, then coalesced writes
    float* smemf = (float*)dsm;
    const int qr = lane >> 2, qc = (lane & 3) * 2;
#pragma unroll
    for (int mf = 0; mf < 4; mf++) {
        const int r0 = wm + mf * 16 + qr;
        const float si0 = g_sqn[i0 + r0], si1 = g_sqn[i0 + r0 + 8];
#pragma unroll
        for (int nf = 0; nf < 4; nf++) {
            const int c0 = wn + nf * 8 + qc;
            const float sj0 = g_sqn[j0 + c0], sj1 = g_sqn[j0 + c0 + 1];
            const float* p = acc[mf][nf];
            float v00 = si0 + sj0 - 2.0f * p[0];
            float v01 = si0 + sj1 - 2.0f * p[1];
            float v10 = si1 + sj0 - 2.0f * p[2];
            float v11 = si1 + sj1 - 2.0f * p[3];
            if (i0 + r0     == j0 + c0)     v00 += 10000000000.0f;
            if (i0 + r0     == j0 + c0 + 1) v01 += 10000000000.0f;
            if (i0 + r0 + 8 == j0 + c0)     v10 += 10000000000.0f;
            if (i0 + r0 + 8 == j0 + c0 + 1) v11 += 10000000000.0f;
            smemf[r0 * SST + c0]           = v00;
            smemf[r0 * SST + c0 + 1]       = v01;
            smemf[(r0 + 8) * SST + c0]     = v10;
            smemf[(r0 + 8) * SST + c0 + 1] = v11;
        }
    }
    __syncthreads();

    {   // direct write: rows i, coalesced float4
        const int row = tid >> 1, seg = tid & 1;
        const float* sr = smemf + row * SST + seg * 64;
        float4* dst = (float4*)(g_dist + (size_t)(i0 + row) * N + j0 + seg * 64);
#pragma unroll
        for (int u = 0; u < 16; u++) dst[u] = *(const float4*)(sr + u * 4);
    }
    if (i0 != j0) {  // mirror write: rows j, gather smem columns
        const int jrow = tid >> 1, seg = tid & 1;
        float* dst = g_dist + (size_t)(j0 + jrow) * N + i0 + seg * 64;
#pragma unroll
        for (int u = 0; u < 16; u++) {
            float4 v;
            v.x = smemf[(seg * 64 + u * 4 + 0) * SST + jrow];
            v.y = smemf[(seg * 64 + u * 4 + 1) * SST + jrow];
            v.z = smemf[(seg * 64 + u * 4 + 2) * SST + jrow];
            v.w = smemf[(seg * 64 + u * 4 + 3) * SST + jrow];
            *(float4*)(dst + u * 4) = v;
        }
    }
}

// ---------------------------------------------------------------------------
// Kernel 3: warp-per-row top-15 + thresholded softmax*mask + batch entropy.
// Contributions with d > dmin+25 are < e^-25 ~ 1.4e-11 each (km<=1) and are
// skipped: total dropped mass < 8192*e^-25 ~ 1.1e-7 << 1e-3 tolerance.
// ---------------------------------------------------------------------------
__device__ __forceinline__ void ins15(float loc[15], float v) {
    if (v < loc[14]) {
        loc[14] = v;
#pragma unroll
        for (int q = 14; q > 0; q--) {
            if (loc[q] < loc[q - 1]) { float tt = loc[q - 1]; loc[q - 1] = loc[q]; loc[q] = tt; }
        }
    }
}

__global__ __launch_bounds__(256) void row_kernel(const int* __restrict__ labels,
                                                  float* __restrict__ out) {
    const int tid  = threadIdx.x;
    const int wid  = tid >> 5;
    const int lane = tid & 31;
    const int row  = blockIdx.x * 8 + wid;

    __shared__ float bsum;
    if (tid == 0) bsum = 0.0f;
    __syncthreads();

    const float4* dr4 = (const float4*)(g_dist + (size_t)row * N);
    const float INF = __int_as_float(0x7f800000);

    // phase 1: per-lane sorted top-15 over 256 elems (64 float4)
    float loc[15];
#pragma unroll
    for (int q = 0; q < 15; q++) loc[q] = INF;
#pragma unroll 4
    for (int k = 0; k < 64; k++) {
        float4 v = dr4[lane + k * 32];
        ins15(loc, v.x); ins15(loc, v.y); ins15(loc, v.z); ins15(loc, v.w);
    }

    // phase 2: 15-round k-way warp merge (shfl min + ballot pop)
    float dmin = 0.0f, kth = 0.0f;
#pragma unroll
    for (int r = 0; r < 15; r++) {
        float h = loc[0];
        float m = h;
#pragma unroll
        for (int o = 16; o > 0; o >>= 1) m = fminf(m, __shfl_xor_sync(0xffffffffu, m, o));
        unsigned ball = __ballot_sync(0xffffffffu, h == m);
        int winner = __ffs(ball) - 1;
        if (lane == winner) {
#pragma unroll
            for (int q = 0; q < 14; q++) loc[q] = loc[q + 1];
            loc[14] = INF;
        }
        if (r == 0)  dmin = m;
        if (r == 14) kth  = m;
    }

    // phase 3: thresholded accumulation (row is L2-hot from phase 1)
    const float thresh = dmin + 25.0f;
    const float C = __expf(dmin - kth);   // exp(d-kth) = C/e
    float Z = 0.f, S = 0.f, s0 = 0.f, s1 = 0.f, s2 = 0.f;
#pragma unroll 2
    for (int k = 0; k < 64; k++) {
        float4 dv = dr4[lane + k * 32];
        const int jb = (lane + k * 32) * 4;
#pragma unroll
        for (int u = 0; u < 4; u++) {
            float d = (u == 0) ? dv.x : (u == 1) ? dv.y : (u == 2) ? dv.z : dv.w;
            if (d < thresh) {
                float e  = __expf(dmin - d);
                float tt = __fdividef(e * e, e + C);   // e * sigmoid(kth-d)
                Z += e; S += tt;
                int lb = labels[jb + u];
                s0 += (lb == 0) ? tt : 0.f;
                s1 += (lb == 1) ? tt : 0.f;
                s2 += (lb == 2) ? tt : 0.f;
            }
        }
    }
#pragma unroll
    for (int o = 16; o > 0; o >>= 1) {
        Z  += __shfl_down_sync(0xffffffffu, Z,  o);
        S  += __shfl_down_sync(0xffffffffu, S,  o);
        s0 += __shfl_down_sync(0xffffffffu, s0, o);
        s1 += __shfl_down_sync(0xffffffffu, s1, o);
        s2 += __shfl_down_sync(0xffffffffu, s2, o);
    }
    if (lane == 0) {
        float denom = S + 1e-8f * Z;
        float p0 = s0 / denom, p1 = s1 / denom, p2 = s2 / denom;
        float H = -(p0 * logf(p0 + 1e-8f) + p1 * logf(p1 + 1e-8f) + p2 * logf(p2 + 1e-8f));
        float nH = H / (logf(3.0f) + 1e-8f);
        atomicAdd(&bsum, -nH * (1.0f / N));
    }
    __syncthreads();
    if (tid == 0) atomicAdd(out, bsum);
}

// ---------------------------------------------------------------------------
extern "C" void kernel_launch(void* const* d_in, const int* in_sizes, int n_in,
                              void* d_out, int out_size) {
    const float* emb    = (const float*)d_in[0];
    const int*   labels = (const int*)d_in[1];
    float*       out    = (float*)d_out;

    cudaFuncSetAttribute(gemm_kernel, cudaFuncAttributeMaxDynamicSharedMemorySize, GEMM_SMEM);

    prep_kernel<<<N / 8, 256>>>(emb, out);
    gemm_kernel<<<64 * 65 / 2, 256, GEMM_SMEM>>>();   // 2080 upper-tri tiles
    row_kernel<<<N / 8, 256>>>(labels, out);
}

// round 10
// speedup vs baseline: 1.5597x; 1.2581x over previous
#include <cuda_runtime.h>
#include <cuda_bf16.h>
#include <cstdint>

#define N 8192
#define D 512

static __device__ float g_cand[(size_t)N * 1024];  // 32 MB: per row, 64 blocks x 16 packed
static __device__ float g_sqn[N];
static __device__ __nv_bfloat16 g_hi[(size_t)N * D];
static __device__ __nv_bfloat16 g_lo[(size_t)N * D];

// ---------------------------------------------------------------------------
// helpers
// ---------------------------------------------------------------------------
__device__ __forceinline__ uint32_t smem_u32(const void* p) {
    uint32_t a;
    asm("{ .reg .u64 t; cvta.to.shared.u64 t, %1; cvt.u32.u64 %0, t; }" : "=r"(a) : "l"(p));
    return a;
}
__device__ __forceinline__ uint32_t sw128(uint32_t b) { return b ^ ((b >> 3) & 0x70); }

__device__ __forceinline__ void cp16(uint32_t dst, const void* src) {
    asm volatile("cp.async.cg.shared.global [%0], [%1], 16;" :: "r"(dst), "l"(src));
}
#define CP_COMMIT() asm volatile("cp.async.commit_group;" ::: "memory")
#define CP_WAIT0()  asm volatile("cp.async.wait_group 0;" ::: "memory")
#define CP_WAIT1()  asm volatile("cp.async.wait_group 1;" ::: "memory")

__device__ __forceinline__ void ldsm_x4(uint32_t* r, uint32_t addr) {
    asm volatile("ldmatrix.sync.aligned.m8n8.x4.shared.b16 {%0,%1,%2,%3}, [%4];"
                 : "=r"(r[0]), "=r"(r[1]), "=r"(r[2]), "=r"(r[3]) : "r"(addr));
}
__device__ __forceinline__ void mma16816(float* d, const uint32_t* a, uint32_t b0, uint32_t b1) {
    asm volatile(
        "mma.sync.aligned.m16n8k16.row.col.f32.bf16.bf16.f32 "
        "{%0,%1,%2,%3}, {%4,%5,%6,%7}, {%8,%9}, {%0,%1,%2,%3};"
        : "+f"(d[0]), "+f"(d[1]), "+f"(d[2]), "+f"(d[3])
        : "r"(a[0]), "r"(a[1]), "r"(a[2]), "r"(a[3]), "r"(b0), "r"(b1));
}

// ---------------------------------------------------------------------------
// Kernel 1: sqnorms + fp32 -> bf16 hi/lo split (one warp per row), zero out
// ---------------------------------------------------------------------------
__global__ void prep_kernel(const float* __restrict__ emb, float* __restrict__ out) {
    if (blockIdx.x == 0 && threadIdx.x == 0) *out = 0.0f;
    int gw   = (blockIdx.x * blockDim.x + threadIdx.x) >> 5;
    int lane = threadIdx.x & 31;
    if (gw >= N) return;
    const float4* src = (const float4*)(emb + (size_t)gw * D);
    float s = 0.0f;
#pragma unroll
    for (int q = 0; q < 4; q++) {
        float4 v = src[lane + q * 32];
        s = fmaf(v.x, v.x, fmaf(v.y, v.y, fmaf(v.z, v.z, fmaf(v.w, v.w, s))));
        __nv_bfloat16 h[4], l[4];
        float f[4] = {v.x, v.y, v.z, v.w};
#pragma unroll
        for (int u = 0; u < 4; u++) {
            h[u] = __float2bfloat16(f[u]);
            l[u] = __float2bfloat16(f[u] - __bfloat162float(h[u]));
        }
        size_t off = (size_t)gw * D + lane * 4 + q * 128;
        *(uint2*)(g_hi + off) = *(const uint2*)h;
        *(uint2*)(g_lo + off) = *(const uint2*)l;
    }
#pragma unroll
    for (int o = 16; o > 0; o >>= 1) s += __shfl_down_sync(0xffffffffu, s, o);
    if (lane == 0) g_sqn[gw] = s;
}

// ---------------------------------------------------------------------------
// Kernel 2: 128x128-tile symmetric distance GEMM via mma.sync bf16-split.
// Upper-triangle tiles (2080 CTAs), 3-stage cp.async pipeline.
// Epilogue: per-row top-16 candidates (label packed into 2 low bits) for
// both the direct rows and (off-diagonal) mirrored columns. No dist matrix.
// ---------------------------------------------------------------------------
#define STAGE_BYTES 32768          // A 16KB + B 16KB per K=64 chunk
#define NSTAGE 3
#define SST 129                    // transpose row stride: odd -> conflict-free both scans
#define LB_OFF 66560               // label arrays offset (128*129*4 = 66048)
#define GEMM_SMEM (NSTAGE * STAGE_BYTES)  // 98304 >= 66560 + 1024
#define NCHUNK 24                  // 3 passes x 8 chunks

__device__ __forceinline__ void ins16(float loc[16], float v) {
    if (v < loc[15]) {
        loc[15] = v;
#pragma unroll
        for (int q = 15; q > 0; q--) {
            if (loc[q] < loc[q - 1]) { float tt = loc[q - 1]; loc[q - 1] = loc[q]; loc[q] = tt; }
        }
    }
}

__device__ __forceinline__ void load_chunk(int c, uint32_t st, int i0, int j0, int tid) {
    const int pass = c >> 3, kc = c & 7;
    const __nv_bfloat16* Asrc = (pass == 2) ? g_lo : g_hi;
    const __nv_bfloat16* Bsrc = (pass == 1) ? g_lo : g_hi;
#pragma unroll
    for (int q = 0; q < 4; q++) {
        int idx = q * 256 + tid;
        int row = idx >> 3, seg = idx & 7;
        cp16(st + sw128(row * 128 + seg * 16),
             Asrc + (size_t)(i0 + row) * D + kc * 64 + seg * 8);
    }
#pragma unroll
    for (int q = 0; q < 4; q++) {
        int idx = q * 256 + tid;
        int row = idx >> 3, seg = idx & 7;
        cp16(st + 16384 + sw128(row * 128 + seg * 16),
             Bsrc + (size_t)(j0 + row) * D + kc * 64 + seg * 8);
    }
    CP_COMMIT();
}

__global__ __launch_bounds__(256, 2) void gemm_kernel(const int* __restrict__ labels) {
    extern __shared__ __align__(1024) uint8_t dsm[];
    const int tid  = threadIdx.x;
    const int wid  = tid >> 5;
    const int lane = tid & 31;

    // upper-triangle tile decode (64x64 grid of 128-tiles)
    int t = blockIdx.x, bi = 0, rem = 64;
    while (t >= rem) { t -= rem; bi++; rem--; }
    const int bj = bi + t;
    const int i0 = bi * 128, j0 = bj * 128;

    const uint32_t dsm_b = smem_u32(dsm);
    const int wm = (wid >> 2) * 64;   // warp m-offset (0/64)
    const int wn = (wid & 3) * 32;    // warp n-offset (0/32/64/96)

    float acc[4][4][4];
#pragma unroll
    for (int a = 0; a < 4; a++)
#pragma unroll
        for (int b = 0; b < 4; b++)
#pragma unroll
            for (int k = 0; k < 4; k++) acc[a][b][k] = 0.0f;

    load_chunk(0, dsm_b, i0, j0, tid);
    load_chunk(1, dsm_b + STAGE_BYTES, i0, j0, tid);

    const uint32_t lrow = lane & 15, lhalf = (lane >> 4) * 16;
    int slot = 0;
    for (int c = 0; c < NCHUNK; c++) {
        if (c + 1 < NCHUNK) CP_WAIT1(); else CP_WAIT0();
        __syncthreads();
        if (c + 2 < NCHUNK) {
            int ns = slot + 2; if (ns >= NSTAGE) ns -= NSTAGE;
            load_chunk(c + 2, dsm_b + ns * STAGE_BYTES, i0, j0, tid);
        }
        const uint32_t stA = dsm_b + slot * STAGE_BYTES;
        const uint32_t stB = stA + 16384;
#pragma unroll
        for (int kk = 0; kk < 4; kk++) {
            uint32_t afr[4][4], bfr[2][4];
#pragma unroll
            for (int mf = 0; mf < 4; mf++)
                ldsm_x4(afr[mf], stA + sw128((wm + mf * 16 + lrow) * 128 + kk * 32 + lhalf));
#pragma unroll
            for (int g = 0; g < 2; g++)
                ldsm_x4(bfr[g], stB + sw128((wn + g * 16 + lrow) * 128 + kk * 32 + lhalf));
#pragma unroll
            for (int mf = 0; mf < 4; mf++)
#pragma unroll
                for (int nf = 0; nf < 4; nf++)
                    mma16816(acc[mf][nf], afr[mf],
                             bfr[nf >> 1][nf & 1], bfr[nf >> 1][(nf & 1) + 2]);
        }
        if (++slot == NSTAGE) slot = 0;
    }
    __syncthreads();   // everyone done reading stages before smem reuse

    // ---- epilogue: distances into smem tile d[r][c], plus label arrays
    float* smemf = (float*)dsm;
    uint32_t* lbA = (uint32_t*)(dsm + LB_OFF);        // labels[i0 + r]
    uint32_t* lbB = lbA + 128;                        // labels[j0 + c]
    if (tid < 128) lbA[tid] = (uint32_t)labels[i0 + tid];
    else           lbB[tid - 128] = (uint32_t)labels[j0 + tid - 128];

    const int qr = lane >> 2, qc = (lane & 3) * 2;
#pragma unroll
    for (int mf = 0; mf < 4; mf++) {
        const int r0 = wm + mf * 16 + qr;
        const float si0 = g_sqn[i0 + r0], si1 = g_sqn[i0 + r0 + 8];
#pragma unroll
        for (int nf = 0; nf < 4; nf++) {
            const int c0 = wn + nf * 8 + qc;
            const float sj0 = g_sqn[j0 + c0], sj1 = g_sqn[j0 + c0 + 1];
            const float* p = acc[mf][nf];
            float v00 = si0 + sj0 - 2.0f * p[0];
            float v01 = si0 + sj1 - 2.0f * p[1];
            float v10 = si1 + sj0 - 2.0f * p[2];
            float v11 = si1 + sj1 - 2.0f * p[3];
            if (i0 + r0     == j0 + c0)     v00 += 10000000000.0f;
            if (i0 + r0     == j0 + c0 + 1) v01 += 10000000000.0f;
            if (i0 + r0 + 8 == j0 + c0)     v10 += 10000000000.0f;
            if (i0 + r0 + 8 == j0 + c0 + 1) v11 += 10000000000.0f;
            smemf[r0 * SST + c0]           = v00;
            smemf[r0 * SST + c0 + 1]       = v01;
            smemf[(r0 + 8) * SST + c0]     = v10;
            smemf[(r0 + 8) * SST + c0 + 1] = v11;
        }
    }
    __syncthreads();

    const float INF = __int_as_float(0x7f800000);
    if (tid < 128) {
        // row scan: row i0+tid, candidates over cols j0..j0+127, pack label of col
        const int r = tid;
        float top[16];
#pragma unroll
        for (int q = 0; q < 16; q++) top[q] = INF;
        const float* base = smemf + r * SST;
        for (int c = 0; c < 128; c++) {
            uint32_t b = (__float_as_uint(base[c]) & ~3u) | lbB[c];
            ins16(top, __uint_as_float(b));
        }
        float4* dst = (float4*)(g_cand + (size_t)(i0 + r) * 1024 + bj * 16);
#pragma unroll
        for (int q = 0; q < 4; q++) dst[q] = *(const float4*)&top[q * 4];
    } else if (i0 != j0) {
        // col scan: row j0+(tid-128), candidates over rows i0..i0+127
        const int c = tid - 128;
        float top[16];
#pragma unroll
        for (int q = 0; q < 16; q++) top[q] = INF;
        for (int u = 0; u < 128; u++) {
            uint32_t b = (__float_as_uint(smemf[u * SST + c]) & ~3u) | lbA[u];
            ins16(top, __uint_as_float(b));
        }
        float4* dst = (float4*)(g_cand + (size_t)(j0 + c) * 1024 + bi * 16);
#pragma unroll
        for (int q = 0; q < 4; q++) dst[q] = *(const float4*)&top[q * 4];
    }
}

// ---------------------------------------------------------------------------
// Kernel 3: warp-per-row over 1024 candidates: exact top-15 (global top-15 is
// a subset of the per-block top-16s) + thresholded softmax*mask + entropy.
// Labels are packed in the 2 low bits of each candidate value.
// ---------------------------------------------------------------------------
__device__ __forceinline__ void ins15(float loc[15], float v) {
    if (v < loc[14]) {
        loc[14] = v;
#pragma unroll
        for (int q = 14; q > 0; q--) {
            if (loc[q] < loc[q - 1]) { float tt = loc[q - 1]; loc[q - 1] = loc[q]; loc[q] = tt; }
        }
    }
}

__global__ __launch_bounds__(256) void row_kernel(float* __restrict__ out) {
    const int tid  = threadIdx.x;
    const int wid  = tid >> 5;
    const int lane = tid & 31;
    const int row  = blockIdx.x * 8 + wid;

    __shared__ float bsum;
    if (tid == 0) bsum = 0.0f;
    __syncthreads();

    const float4* cr = (const float4*)(g_cand + (size_t)row * 1024);
    const float INF = __int_as_float(0x7f800000);

    // phase 1: per-lane top-15 over 32 candidates + cache in regs
    float cv[32];
    float loc[15];
#pragma unroll
    for (int q = 0; q < 15; q++) loc[q] = INF;
#pragma unroll
    for (int k = 0; k < 8; k++) {
        float4 v = cr[lane + k * 32];
        cv[k * 4 + 0] = v.x; cv[k * 4 + 1] = v.y; cv[k * 4 + 2] = v.z; cv[k * 4 + 3] = v.w;
        ins15(loc, v.x); ins15(loc, v.y); ins15(loc, v.z); ins15(loc, v.w);
    }

    // phase 2: 15-round warp merge
    float dmin = 0.0f, kth = 0.0f;
#pragma unroll
    for (int r = 0; r < 15; r++) {
        float h = loc[0];
        float m = h;
#pragma unroll
        for (int o = 16; o > 0; o >>= 1) m = fminf(m, __shfl_xor_sync(0xffffffffu, m, o));
        unsigned ball = __ballot_sync(0xffffffffu, h == m);
        int winner = __ffs(ball) - 1;
        if (lane == winner) {
#pragma unroll
            for (int q = 0; q < 14; q++) loc[q] = loc[q + 1];
            loc[14] = INF;
        }
        if (r == 0)  dmin = m;
        if (r == 14) kth  = m;
    }

    // phase 3: thresholded accumulation over register-cached candidates
    const float thresh = dmin + 25.0f;
    const float C = __expf(dmin - kth);
    float Z = 0.f, S = 0.f, s0 = 0.f, s1 = 0.f, s2 = 0.f;
#pragma unroll
    for (int u = 0; u < 32; u++) {
        float d = cv[u];
        if (d < thresh) {
            float e  = __expf(dmin - d);
            float tt = __fdividef(e * e, e + C);   // e * sigmoid(kth-d)
            Z += e; S += tt;
            int lb = __float_as_uint(d) & 3u;
            s0 += (lb == 0) ? tt : 0.f;
            s1 += (lb == 1) ? tt : 0.f;
            s2 += (lb == 2) ? tt : 0.f;
        }
    }
#pragma unroll
    for (int o = 16; o > 0; o >>= 1) {
        Z  += __shfl_down_sync(0xffffffffu, Z,  o);
        S  += __shfl_down_sync(0xffffffffu, S,  o);
        s0 += __shfl_down_sync(0xffffffffu, s0, o);
        s1 += __shfl_down_sync(0xffffffffu, s1, o);
        s2 += __shfl_down_sync(0xffffffffu, s2, o);
    }
    if (lane == 0) {
        float denom = S + 1e-8f * Z;
        float p0 = s0 / denom, p1 = s1 / denom, p2 = s2 / denom;
        float H = -(p0 * logf(p0 + 1e-8f) + p1 * logf(p1 + 1e-8f) + p2 * logf(p2 + 1e-8f));
        float nH = H / (logf(3.0f) + 1e-8f);
        atomicAdd(&bsum, -nH * (1.0f / N));
    }
    __syncthreads();
    if (tid == 0) atomicAdd(out, bsum);
}

// ---------------------------------------------------------------------------
extern "C" void kernel_launch(void* const* d_in, const int* in_sizes, int n_in,
                              void* d_out, int out_size) {
    const float* emb    = (const float*)d_in[0];
    const int*   labels = (const int*)d_in[1];
    float*       out    = (float*)d_out;

    cudaFuncSetAttribute(gemm_kernel, cudaFuncAttributeMaxDynamicSharedMemorySize, GEMM_SMEM);

    prep_kernel<<<N / 8, 256>>>(emb, out);
    gemm_kernel<<<64 * 65 / 2, 256, GEMM_SMEM>>>(labels);   // 2080 upper-tri tiles
    row_kernel<<<N / 8, 256>>>(out);
}

// round 11
// speedup vs baseline: 1.9141x; 1.2272x over previous
#include <cuda_runtime.h>
#include <cuda_fp16.h>
#include <cstdint>

#define N 8192
#define D 512

static __device__ float g_cand[(size_t)N * 1024];  // 32 MB: per row, 64 blocks x 16 packed
static __device__ float g_sqn[N];
static __device__ __half g_hi[(size_t)N * D];
static __device__ __half g_lo[(size_t)N * D];

// ---------------------------------------------------------------------------
// helpers
// ---------------------------------------------------------------------------
__device__ __forceinline__ uint32_t smem_u32(const void* p) {
    uint32_t a;
    asm("{ .reg .u64 t; cvta.to.shared.u64 t, %1; cvt.u32.u64 %0, t; }" : "=r"(a) : "l"(p));
    return a;
}
__device__ __forceinline__ uint32_t sw128(uint32_t b) { return b ^ ((b >> 3) & 0x70); }

__device__ __forceinline__ void cp16(uint32_t dst, const void* src) {
    asm volatile("cp.async.cg.shared.global [%0], [%1], 16;" :: "r"(dst), "l"(src));
}
#define CP_COMMIT() asm volatile("cp.async.commit_group;" ::: "memory")
#define CP_WAIT0()  asm volatile("cp.async.wait_group 0;" ::: "memory")
#define CP_WAIT1()  asm volatile("cp.async.wait_group 1;" ::: "memory")

__device__ __forceinline__ void ldsm_x4(uint32_t* r, uint32_t addr) {
    asm volatile("ldmatrix.sync.aligned.m8n8.x4.shared.b16 {%0,%1,%2,%3}, [%4];"
                 : "=r"(r[0]), "=r"(r[1]), "=r"(r[2]), "=r"(r[3]) : "r"(addr));
}
__device__ __forceinline__ void mma16816(float* d, const uint32_t* a, uint32_t b0, uint32_t b1) {
    asm volatile(
        "mma.sync.aligned.m16n8k16.row.col.f32.f16.f16.f32 "
        "{%0,%1,%2,%3}, {%4,%5,%6,%7}, {%8,%9}, {%0,%1,%2,%3};"
        : "+f"(d[0]), "+f"(d[1]), "+f"(d[2]), "+f"(d[3])
        : "r"(a[0]), "r"(a[1]), "r"(a[2]), "r"(a[3]), "r"(b0), "r"(b1));
}

// ---------------------------------------------------------------------------
// Kernel 1: sqnorms + fp32 -> fp16 hi/lo split (one warp per row), zero out
// ---------------------------------------------------------------------------
__global__ void prep_kernel(const float* __restrict__ emb, float* __restrict__ out) {
    if (blockIdx.x == 0 && threadIdx.x == 0) *out = 0.0f;
    int gw   = (blockIdx.x * blockDim.x + threadIdx.x) >> 5;
    int lane = threadIdx.x & 31;
    if (gw >= N) return;
    const float4* src = (const float4*)(emb + (size_t)gw * D);
    float s = 0.0f;
#pragma unroll
    for (int q = 0; q < 4; q++) {
        float4 v = src[lane + q * 32];
        s = fmaf(v.x, v.x, fmaf(v.y, v.y, fmaf(v.z, v.z, fmaf(v.w, v.w, s))));
        __half h[4], l[4];
        float f[4] = {v.x, v.y, v.z, v.w};
#pragma unroll
        for (int u = 0; u < 4; u++) {
            h[u] = __float2half(f[u]);
            l[u] = __float2half(f[u] - __half2float(h[u]));
        }
        size_t off = (size_t)gw * D + lane * 4 + q * 128;
        *(uint2*)(g_hi + off) = *(const uint2*)h;
        *(uint2*)(g_lo + off) = *(const uint2*)l;
    }
#pragma unroll
    for (int o = 16; o > 0; o >>= 1) s += __shfl_down_sync(0xffffffffu, s, o);
    if (lane == 0) g_sqn[gw] = s;
}

// ---------------------------------------------------------------------------
// Kernel 2: 128x128-tile symmetric distance GEMM via mma.sync fp16-split.
// 2 passes (A_hi*B_hi + A_hi*B_lo); dropped lo*hi term < ~0.02 on d (harmless).
// Upper-triangle tiles (2080 CTAs), 3-stage cp.async pipeline.
// Epilogue: per-row top-16 candidates (label packed into 2 low bits).
// ---------------------------------------------------------------------------
#define STAGE_BYTES 32768          // A 16KB + B 16KB per K=64 chunk
#define NSTAGE 3
#define SST 129                    // transpose row stride: odd -> conflict-free both scans
#define LB_OFF 66560               // label arrays offset (128*129*4 = 66048)
#define GEMM_SMEM (NSTAGE * STAGE_BYTES)  // 98304 >= 66560 + 1024
#define NCHUNK 16                  // 2 passes x 8 chunks

__device__ __forceinline__ void ins16(float loc[16], float v) {
    if (v < loc[15]) {
        loc[15] = v;
#pragma unroll
        for (int q = 15; q > 0; q--) {
            if (loc[q] < loc[q - 1]) { float tt = loc[q - 1]; loc[q - 1] = loc[q]; loc[q] = tt; }
        }
    }
}

__device__ __forceinline__ void load_chunk(int c, uint32_t st, int i0, int j0, int tid) {
    const int pass = c >> 3, kc = c & 7;
    const __half* Bsrc = pass ? g_lo : g_hi;   // A is always hi
#pragma unroll
    for (int q = 0; q < 4; q++) {
        int idx = q * 256 + tid;
        int row = idx >> 3, seg = idx & 7;
        cp16(st + sw128(row * 128 + seg * 16),
             g_hi + (size_t)(i0 + row) * D + kc * 64 + seg * 8);
    }
#pragma unroll
    for (int q = 0; q < 4; q++) {
        int idx = q * 256 + tid;
        int row = idx >> 3, seg = idx & 7;
        cp16(st + 16384 + sw128(row * 128 + seg * 16),
             Bsrc + (size_t)(j0 + row) * D + kc * 64 + seg * 8);
    }
    CP_COMMIT();
}

__global__ __launch_bounds__(256, 2) void gemm_kernel(const int* __restrict__ labels) {
    extern __shared__ __align__(1024) uint8_t dsm[];
    const int tid  = threadIdx.x;
    const int wid  = tid >> 5;
    const int lane = tid & 31;

    // upper-triangle tile decode (64x64 grid of 128-tiles)
    int t = blockIdx.x, bi = 0, rem = 64;
    while (t >= rem) { t -= rem; bi++; rem--; }
    const int bj = bi + t;
    const int i0 = bi * 128, j0 = bj * 128;

    const uint32_t dsm_b = smem_u32(dsm);
    const int wm = (wid >> 2) * 64;   // warp m-offset (0/64)
    const int wn = (wid & 3) * 32;    // warp n-offset (0/32/64/96)

    float acc[4][4][4];
#pragma unroll
    for (int a = 0; a < 4; a++)
#pragma unroll
        for (int b = 0; b < 4; b++)
#pragma unroll
            for (int k = 0; k < 4; k++) acc[a][b][k] = 0.0f;

    load_chunk(0, dsm_b, i0, j0, tid);
    load_chunk(1, dsm_b + STAGE_BYTES, i0, j0, tid);

    const uint32_t lrow = lane & 15, lhalf = (lane >> 4) * 16;
    int slot = 0;
    for (int c = 0; c < NCHUNK; c++) {
        if (c + 1 < NCHUNK) CP_WAIT1(); else CP_WAIT0();
        __syncthreads();
        if (c + 2 < NCHUNK) {
            int ns = slot + 2; if (ns >= NSTAGE) ns -= NSTAGE;
            load_chunk(c + 2, dsm_b + ns * STAGE_BYTES, i0, j0, tid);
        }
        const uint32_t stA = dsm_b + slot * STAGE_BYTES;
        const uint32_t stB = stA + 16384;
#pragma unroll
        for (int kk = 0; kk < 4; kk++) {
            uint32_t afr[4][4], bfr[2][4];
#pragma unroll
            for (int mf = 0; mf < 4; mf++)
                ldsm_x4(afr[mf], stA + sw128((wm + mf * 16 + lrow) * 128 + kk * 32 + lhalf));
#pragma unroll
            for (int g = 0; g < 2; g++)
                ldsm_x4(bfr[g], stB + sw128((wn + g * 16 + lrow) * 128 + kk * 32 + lhalf));
#pragma unroll
            for (int mf = 0; mf < 4; mf++)
#pragma unroll
                for (int nf = 0; nf < 4; nf++)
                    mma16816(acc[mf][nf], afr[mf],
                             bfr[nf >> 1][nf & 1], bfr[nf >> 1][(nf & 1) + 2]);
        }
        if (++slot == NSTAGE) slot = 0;
    }
    __syncthreads();   // everyone done reading stages before smem reuse

    // ---- epilogue: distances into smem tile d[r][c], plus label arrays
    float* smemf = (float*)dsm;
    uint32_t* lbA = (uint32_t*)(dsm + LB_OFF);        // labels[i0 + r]
    uint32_t* lbB = lbA + 128;                        // labels[j0 + c]
    if (tid < 128) lbA[tid] = (uint32_t)labels[i0 + tid];
    else           lbB[tid - 128] = (uint32_t)labels[j0 + tid - 128];

    const int qr = lane >> 2, qc = (lane & 3) * 2;
#pragma unroll
    for (int mf = 0; mf < 4; mf++) {
        const int r0 = wm + mf * 16 + qr;
        const float si0 = g_sqn[i0 + r0], si1 = g_sqn[i0 + r0 + 8];
#pragma unroll
        for (int nf = 0; nf < 4; nf++) {
            const int c0 = wn + nf * 8 + qc;
            const float sj0 = g_sqn[j0 + c0], sj1 = g_sqn[j0 + c0 + 1];
            const float* p = acc[mf][nf];
            float v00 = si0 + sj0 - 2.0f * p[0];
            float v01 = si0 + sj1 - 2.0f * p[1];
            float v10 = si1 + sj0 - 2.0f * p[2];
            float v11 = si1 + sj1 - 2.0f * p[3];
            if (i0 + r0     == j0 + c0)     v00 += 10000000000.0f;
            if (i0 + r0     == j0 + c0 + 1) v01 += 10000000000.0f;
            if (i0 + r0 + 8 == j0 + c0)     v10 += 10000000000.0f;
            if (i0 + r0 + 8 == j0 + c0 + 1) v11 += 10000000000.0f;
            smemf[r0 * SST + c0]           = v00;
            smemf[r0 * SST + c0 + 1]       = v01;
            smemf[(r0 + 8) * SST + c0]     = v10;
            smemf[(r0 + 8) * SST + c0 + 1] = v11;
        }
    }
    __syncthreads();

    const float INF = __int_as_float(0x7f800000);
    if (tid < 128) {
        // row scan: row i0+tid, candidates over cols j0..j0+127, pack label of col
        const int r = tid;
        float top[16];
#pragma unroll
        for (int q = 0; q < 16; q++) top[q] = INF;
        const float* base = smemf + r * SST;
        for (int c = 0; c < 128; c++) {
            uint32_t b = (__float_as_uint(base[c]) & ~3u) | lbB[c];
            ins16(top, __uint_as_float(b));
        }
        float4* dst = (float4*)(g_cand + (size_t)(i0 + r) * 1024 + bj * 16);
#pragma unroll
        for (int q = 0; q < 4; q++) dst[q] = *(const float4*)&top[q * 4];
    } else if (i0 != j0) {
        // col scan: row j0+(tid-128), candidates over rows i0..i0+127
        const int c = tid - 128;
        float top[16];
#pragma unroll
        for (int q = 0; q < 16; q++) top[q] = INF;
        for (int u = 0; u < 128; u++) {
            uint32_t b = (__float_as_uint(smemf[u * SST + c]) & ~3u) | lbA[u];
            ins16(top, __uint_as_float(b));
        }
        float4* dst = (float4*)(g_cand + (size_t)(j0 + c) * 1024 + bi * 16);
#pragma unroll
        for (int q = 0; q < 4; q++) dst[q] = *(const float4*)&top[q * 4];
    }
}

// ---------------------------------------------------------------------------
// Kernel 3: warp-per-row over 1024 candidates: exact top-15 + thresholded
// softmax*mask + entropy. Labels packed in 2 low bits of each candidate.
// ---------------------------------------------------------------------------
__device__ __forceinline__ void ins15(float loc[15], float v) {
    if (v < loc[14]) {
        loc[14] = v;
#pragma unroll
        for (int q = 14; q > 0; q--) {
            if (loc[q] < loc[q - 1]) { float tt = loc[q - 1]; loc[q - 1] = loc[q]; loc[q] = tt; }
        }
    }
}

__global__ __launch_bounds__(256) void row_kernel(float* __restrict__ out) {
    const int tid  = threadIdx.x;
    const int wid  = tid >> 5;
    const int lane = tid & 31;
    const int row  = blockIdx.x * 8 + wid;

    __shared__ float bsum;
    if (tid == 0) bsum = 0.0f;
    __syncthreads();

    const float4* cr = (const float4*)(g_cand + (size_t)row * 1024);
    const float INF = __int_as_float(0x7f800000);

    // phase 1: per-lane top-15 over 32 candidates + cache in regs
    float cv[32];
    float loc[15];
#pragma unroll
    for (int q = 0; q < 15; q++) loc[q] = INF;
#pragma unroll
    for (int k = 0; k < 8; k++) {
        float4 v = cr[lane + k * 32];
        cv[k * 4 + 0] = v.x; cv[k * 4 + 1] = v.y; cv[k * 4 + 2] = v.z; cv[k * 4 + 3] = v.w;
        ins15(loc, v.x); ins15(loc, v.y); ins15(loc, v.z); ins15(loc, v.w);
    }

    // phase 2: 15-round warp merge
    float dmin = 0.0f, kth = 0.0f;
#pragma unroll
    for (int r = 0; r < 15; r++) {
        float h = loc[0];
        float m = h;
#pragma unroll
        for (int o = 16; o > 0; o >>= 1) m = fminf(m, __shfl_xor_sync(0xffffffffu, m, o));
        unsigned ball = __ballot_sync(0xffffffffu, h == m);
        int winner = __ffs(ball) - 1;
        if (lane == winner) {
#pragma unroll
            for (int q = 0; q < 14; q++) loc[q] = loc[q + 1];
            loc[14] = INF;
        }
        if (r == 0)  dmin = m;
        if (r == 14) kth  = m;
    }

    // phase 3: thresholded accumulation over register-cached candidates
    const float thresh = dmin + 25.0f;
    const float C = __expf(dmin - kth);
    float Z = 0.f, S = 0.f, s0 = 0.f, s1 = 0.f, s2 = 0.f;
#pragma unroll
    for (int u = 0; u < 32; u++) {
        float d = cv[u];
        if (d < thresh) {
            float e  = __expf(dmin - d);
            float tt = __fdividef(e * e, e + C);   // e * sigmoid(kth-d)
            Z += e; S += tt;
            int lb = __float_as_uint(d) & 3u;
            s0 += (lb == 0) ? tt : 0.f;
            s1 += (lb == 1) ? tt : 0.f;
            s2 += (lb == 2) ? tt : 0.f;
        }
    }
#pragma unroll
    for (int o = 16; o > 0; o >>= 1) {
        Z  += __shfl_down_sync(0xffffffffu, Z,  o);
        S  += __shfl_down_sync(0xffffffffu, S,  o);
        s0 += __shfl_down_sync(0xffffffffu, s0, o);
        s1 += __shfl_down_sync(0xffffffffu, s1, o);
        s2 += __shfl_down_sync(0xffffffffu, s2, o);
    }
    if (lane == 0) {
        float denom = S + 1e-8f * Z;
        float p0 = s0 / denom, p1 = s1 / denom, p2 = s2 / denom;
        float H = -(p0 * logf(p0 + 1e-8f) + p1 * logf(p1 + 1e-8f) + p2 * logf(p2 + 1e-8f));
        float nH = H / (logf(3.0f) + 1e-8f);
        atomicAdd(&bsum, -nH * (1.0f / N));
    }
    __syncthreads();
    if (tid == 0) atomicAdd(out, bsum);
}

// ---------------------------------------------------------------------------
extern "C" void kernel_launch(void* const* d_in, const int* in_sizes, int n_in,
                              void* d_out, int out_size) {
    const float* emb    = (const float*)d_in[0];
    const int*   labels = (const int*)d_in[1];
    float*       out    = (float*)d_out;

    cudaFuncSetAttribute(gemm_kernel, cudaFuncAttributeMaxDynamicSharedMemorySize, GEMM_SMEM);

    prep_kernel<<<N / 8, 256>>>(emb, out);
    gemm_kernel<<<64 * 65 / 2, 256, GEMM_SMEM>>>(labels);   // 2080 upper-tri tiles
    row_kernel<<<N / 8, 256>>>(out);
}

// round 13
// speedup vs baseline: 2.3811x; 1.2440x over previous
#include <cuda_runtime.h>
#include <cuda_fp16.h>
#include <cstdint>

#define N 8192
#define D 512

static __device__ float g_cand[(size_t)N * 1024];  // 32 MB: per row, 64 blocks x 16 packed
static __device__ float g_sqn[N];
static __device__ __half g_hi[(size_t)N * D];

// ---------------------------------------------------------------------------
// helpers
// ---------------------------------------------------------------------------
__device__ __forceinline__ uint32_t smem_u32(const void* p) {
    uint32_t a;
    asm("{ .reg .u64 t; cvta.to.shared.u64 t, %1; cvt.u32.u64 %0, t; }" : "=r"(a) : "l"(p));
    return a;
}
__device__ __forceinline__ uint32_t sw128(uint32_t b) { return b ^ ((b >> 3) & 0x70); }

__device__ __forceinline__ void cp16(uint32_t dst, const void* src) {
    asm volatile("cp.async.cg.shared.global [%0], [%1], 16;" :: "r"(dst), "l"(src));
}
#define CP_COMMIT() asm volatile("cp.async.commit_group;" ::: "memory")
#define CP_WAIT0()  asm volatile("cp.async.wait_group 0;" ::: "memory")
#define CP_WAIT1()  asm volatile("cp.async.wait_group 1;" ::: "memory")

__device__ __forceinline__ void ldsm_x4(uint32_t* r, uint32_t addr) {
    asm volatile("ldmatrix.sync.aligned.m8n8.x4.shared.b16 {%0,%1,%2,%3}, [%4];"
                 : "=r"(r[0]), "=r"(r[1]), "=r"(r[2]), "=r"(r[3]) : "r"(addr));
}
__device__ __forceinline__ void mma16816(float* d, const uint32_t* a, uint32_t b0, uint32_t b1) {
    asm volatile(
        "mma.sync.aligned.m16n8k16.row.col.f32.f16.f16.f32 "
        "{%0,%1,%2,%3}, {%4,%5,%6,%7}, {%8,%9}, {%0,%1,%2,%3};"
        : "+f"(d[0]), "+f"(d[1]), "+f"(d[2]), "+f"(d[3])
        : "r"(a[0]), "r"(a[1]), "r"(a[2]), "r"(a[3]), "r"(b0), "r"(b1));
}

// ---------------------------------------------------------------------------
// Kernel 1: sqnorms + fp32 -> fp16 (one warp per row), zero out
// ---------------------------------------------------------------------------
__global__ void prep_kernel(const float* __restrict__ emb, float* __restrict__ out) {
    if (blockIdx.x == 0 && threadIdx.x == 0) *out = 0.0f;
    int gw   = (blockIdx.x * blockDim.x + threadIdx.x) >> 5;
    int lane = threadIdx.x & 31;
    if (gw >= N) return;
    const float4* src = (const float4*)(emb + (size_t)gw * D);
    float s = 0.0f;
#pragma unroll
    for (int q = 0; q < 4; q++) {
        float4 v = src[lane + q * 32];
        s = fmaf(v.x, v.x, fmaf(v.y, v.y, fmaf(v.z, v.z, fmaf(v.w, v.w, s))));
        __half h[4];
        float f[4] = {v.x, v.y, v.z, v.w};
#pragma unroll
        for (int u = 0; u < 4; u++) h[u] = __float2half(f[u]);
        *(uint2*)(g_hi + (size_t)gw * D + lane * 4 + q * 128) = *(const uint2*)h;
    }
#pragma unroll
    for (int o = 16; o > 0; o >>= 1) s += __shfl_down_sync(0xffffffffu, s, o);
    if (lane == 0) g_sqn[gw] = s;
}

// ---------------------------------------------------------------------------
// Kernel 2: 128x128-tile symmetric distance GEMM via mma.sync fp16 (hi only).
// Single pass over K (8 chunks). Dropped fp16 cross/lo terms perturb d by
// ~0.02 (measured ~8e-5 loss-error per cross term). Upper-triangle tiles,
// 3-stage cp.async pipeline. Epilogue: per-row top-16 candidates
// (label packed into 2 low bits), direct rows + mirrored columns.
// ---------------------------------------------------------------------------
#define STAGE_BYTES 32768          // A 16KB + B 16KB per K=64 chunk
#define NSTAGE 3
#define SST 129                    // transpose row stride: odd -> conflict-free both scans
#define LB_OFF 66560               // label arrays offset (128*129*4 = 66048)
#define GEMM_SMEM (NSTAGE * STAGE_BYTES)  // 98304 >= 66560 + 1024
#define NCHUNK 8                   // 1 pass x 8 k-chunks of 64

__device__ __forceinline__ void ins16(float loc[16], float v) {
    if (v < loc[15]) {
        loc[15] = v;
#pragma unroll
        for (int q = 15; q > 0; q--) {
            if (loc[q] < loc[q - 1]) { float tt = loc[q - 1]; loc[q - 1] = loc[q]; loc[q] = tt; }
        }
    }
}

__device__ __forceinline__ void load_chunk(int kc, uint32_t st, int i0, int j0, int tid) {
#pragma unroll
    for (int q = 0; q < 4; q++) {
        int idx = q * 256 + tid;
        int row = idx >> 3, seg = idx & 7;
        cp16(st + sw128(row * 128 + seg * 16),
             g_hi + (size_t)(i0 + row) * D + kc * 64 + seg * 8);
    }
#pragma unroll
    for (int q = 0; q < 4; q++) {
        int idx = q * 256 + tid;
        int row = idx >> 3, seg = idx & 7;
        cp16(st + 16384 + sw128(row * 128 + seg * 16),
             g_hi + (size_t)(j0 + row) * D + kc * 64 + seg * 8);
    }
    CP_COMMIT();
}

__global__ __launch_bounds__(256, 2) void gemm_kernel(const int* __restrict__ labels) {
    extern __shared__ __align__(1024) uint8_t dsm[];
    const int tid  = threadIdx.x;
    const int wid  = tid >> 5;
    const int lane = tid & 31;

    // upper-triangle tile decode (64x64 grid of 128-tiles)
    int t = blockIdx.x, bi = 0, rem = 64;
    while (t >= rem) { t -= rem; bi++; rem--; }
    const int bj = bi + t;
    const int i0 = bi * 128, j0 = bj * 128;

    const uint32_t dsm_b = smem_u32(dsm);
    const int wm = (wid >> 2) * 64;   // warp m-offset (0/64)
    const int wn = (wid & 3) * 32;    // warp n-offset (0/32/64/96)

    float acc[4][4][4];
#pragma unroll
    for (int a = 0; a < 4; a++)
#pragma unroll
        for (int b = 0; b < 4; b++)
#pragma unroll
            for (int k = 0; k < 4; k++) acc[a][b][k] = 0.0f;

    load_chunk(0, dsm_b, i0, j0, tid);
    load_chunk(1, dsm_b + STAGE_BYTES, i0, j0, tid);

    const uint32_t lrow = lane & 15, lhalf = (lane >> 4) * 16;
    int slot = 0;
    for (int c = 0; c < NCHUNK; c++) {
        if (c + 1 < NCHUNK) CP_WAIT1(); else CP_WAIT0();
        __syncthreads();
        if (c + 2 < NCHUNK) {
            int ns = slot + 2; if (ns >= NSTAGE) ns -= NSTAGE;
            load_chunk(c + 2, dsm_b + ns * STAGE_BYTES, i0, j0, tid);
        }
        const uint32_t stA = dsm_b + slot * STAGE_BYTES;
        const uint32_t stB = stA + 16384;
#pragma unroll
        for (int kk = 0; kk < 4; kk++) {
            uint32_t afr[4][4], bfr[2][4];
#pragma unroll
            for (int mf = 0; mf < 4; mf++)
                ldsm_x4(afr[mf], stA + sw128((wm + mf * 16 + lrow) * 128 + kk * 32 + lhalf));
#pragma unroll
            for (int g = 0; g < 2; g++)
                ldsm_x4(bfr[g], stB + sw128((wn + g * 16 + lrow) * 128 + kk * 32 + lhalf));
#pragma unroll
            for (int mf = 0; mf < 4; mf++)
#pragma unroll
                for (int nf = 0; nf < 4; nf++)
                    mma16816(acc[mf][nf], afr[mf],
                             bfr[nf >> 1][nf & 1], bfr[nf >> 1][(nf & 1) + 2]);
        }
        if (++slot == NSTAGE) slot = 0;
    }
    __syncthreads();   // everyone done reading stages before smem reuse

    // ---- epilogue: distances into smem tile d[r][c], plus label arrays
    float* smemf = (float*)dsm;
    uint32_t* lbA = (uint32_t*)(dsm + LB_OFF);        // labels[i0 + r]
    uint32_t* lbB = lbA + 128;                        // labels[j0 + c]
    if (tid < 128) lbA[tid] = (uint32_t)labels[i0 + tid];
    else           lbB[tid - 128] = (uint32_t)labels[j0 + tid - 128];

    const int qr = lane >> 2, qc = (lane & 3) * 2;
#pragma unroll
    for (int mf = 0; mf < 4; mf++) {
        const int r0 = wm + mf * 16 + qr;
        const float si0 = g_sqn[i0 + r0], si1 = g_sqn[i0 + r0 + 8];
#pragma unroll
        for (int nf = 0; nf < 4; nf++) {
            const int c0 = wn + nf * 8 + qc;
            const float sj0 = g_sqn[j0 + c0], sj1 = g_sqn[j0 + c0 + 1];
            const float* p = acc[mf][nf];
            float v00 = si0 + sj0 - 2.0f * p[0];
            float v01 = si0 + sj1 - 2.0f * p[1];
            float v10 = si1 + sj0 - 2.0f * p[2];
            float v11 = si1 + sj1 - 2.0f * p[3];
            if (i0 + r0     == j0 + c0)     v00 += 10000000000.0f;
            if (i0 + r0     == j0 + c0 + 1) v01 += 10000000000.0f;
            if (i0 + r0 + 8 == j0 + c0)     v10 += 10000000000.0f;
            if (i0 + r0 + 8 == j0 + c0 + 1) v11 += 10000000000.0f;
            smemf[r0 * SST + c0]           = v00;
            smemf[r0 * SST + c0 + 1]       = v01;
            smemf[(r0 + 8) * SST + c0]     = v10;
            smemf[(r0 + 8) * SST + c0 + 1] = v11;
        }
    }
    __syncthreads();

    const float INF = __int_as_float(0x7f800000);
    if (tid < 128) {
        // row scan: row i0+tid, candidates over cols j0..j0+127, pack label of col
        const int r = tid;
        float top[16];
#pragma unroll
        for (int q = 0; q < 16; q++) top[q] = INF;
        const float* base = smemf + r * SST;
        for (int c = 0; c < 128; c++) {
            uint32_t b = (__float_as_uint(base[c]) & ~3u) | lbB[c];
            ins16(top, __uint_as_float(b));
        }
        float4* dst = (float4*)(g_cand + (size_t)(i0 + r) * 1024 + bj * 16);
#pragma unroll
        for (int q = 0; q < 4; q++) dst[q] = *(const float4*)&top[q * 4];
    } else if (i0 != j0) {
        // col scan: row j0+(tid-128), candidates over rows i0..i0+127
        const int c = tid - 128;
        float top[16];
#pragma unroll
        for (int q = 0; q < 16; q++) top[q] = INF;
        for (int u = 0; u < 128; u++) {
            uint32_t b = (__float_as_uint(smemf[u * SST + c]) & ~3u) | lbA[u];
            ins16(top, __uint_as_float(b));
        }
        float4* dst = (float4*)(g_cand + (size_t)(j0 + c) * 1024 + bi * 16);
#pragma unroll
        for (int q = 0; q < 4; q++) dst[q] = *(const float4*)&top[q * 4];
    }
}

// ---------------------------------------------------------------------------
// Kernel 3: warp-per-row over 1024 candidates: exact top-15 + thresholded
// softmax*mask + entropy. Labels packed in 2 low bits of each candidate.
// ---------------------------------------------------------------------------
__device__ __forceinline__ void ins15(float loc[15], float v) {
    if (v < loc[14]) {
        loc[14] = v;
#pragma unroll
        for (int q = 14; q > 0; q--) {
            if (loc[q] < loc[q - 1]) { float tt = loc[q - 1]; loc[q - 1] = loc[q]; loc[q] = tt; }
        }
    }
}

__global__ __launch_bounds__(256) void row_kernel(float* __restrict__ out) {
    const int tid  = threadIdx.x;
    const int wid  = tid >> 5;
    const int lane = tid & 31;
    const int row  = blockIdx.x * 8 + wid;

    __shared__ float bsum;
    if (tid == 0) bsum = 0.0f;
    __syncthreads();

    const float4* cr = (const float4*)(g_cand + (size_t)row * 1024);
    const float INF = __int_as_float(0x7f800000);

    // phase 1: per-lane top-15 over 32 candidates + cache in regs
    float cv[32];
    float loc[15];
#pragma unroll
    for (int q = 0; q < 15; q++) loc[q] = INF;
#pragma unroll
    for (int k = 0; k < 8; k++) {
        float4 v = cr[lane + k * 32];
        cv[k * 4 + 0] = v.x; cv[k * 4 + 1] = v.y; cv[k * 4 + 2] = v.z; cv[k * 4 + 3] = v.w;
        ins15(loc, v.x); ins15(loc, v.y); ins15(loc, v.z); ins15(loc, v.w);
    }

    // phase 2: 15-round warp merge
    float dmin = 0.0f, kth = 0.0f;
#pragma unroll
    for (int r = 0; r < 15; r++) {
        float h = loc[0];
        float m = h;
#pragma unroll
        for (int o = 16; o > 0; o >>= 1) m = fminf(m, __shfl_xor_sync(0xffffffffu, m, o));
        unsigned ball = __ballot_sync(0xffffffffu, h == m);
        int winner = __ffs(ball) - 1;
        if (lane == winner) {
#pragma unroll
            for (int q = 0; q < 14; q++) loc[q] = loc[q + 1];
            loc[14] = INF;
        }
        if (r == 0)  dmin = m;
        if (r == 14) kth  = m;
    }

    // phase 3: thresholded accumulation over register-cached candidates
    const float thresh = dmin + 25.0f;
    const float C = __expf(dmin - kth);
    float Z = 0.f, S = 0.f, s0 = 0.f, s1 = 0.f, s2 = 0.f;
#pragma unroll
    for (int u = 0; u < 32; u++) {
        float d = cv[u];
        if (d < thresh) {
            float e  = __expf(dmin - d);
            float tt = __fdividef(e * e, e + C);   // e * sigmoid(kth-d)
            Z += e; S += tt;
            int lb = __float_as_uint(d) & 3u;
            s0 += (lb == 0) ? tt : 0.f;
            s1 += (lb == 1) ? tt : 0.f;
            s2 += (lb == 2) ? tt : 0.f;
        }
    }
#pragma unroll
    for (int o = 16; o > 0; o >>= 1) {
        Z  += __shfl_down_sync(0xffffffffu, Z,  o);
        S  += __shfl_down_sync(0xffffffffu, S,  o);
        s0 += __shfl_down_sync(0xffffffffu, s0, o);
        s1 += __shfl_down_sync(0xffffffffu, s1, o);
        s2 += __shfl_down_sync(0xffffffffu, s2, o);
    }
    if (lane == 0) {
        float denom = S + 1e-8f * Z;
        float p0 = s0 / denom, p1 = s1 / denom, p2 = s2 / denom;
        float H = -(p0 * logf(p0 + 1e-8f) + p1 * logf(p1 + 1e-8f) + p2 * logf(p2 + 1e-8f));
        float nH = H / (logf(3.0f) + 1e-8f);
        atomicAdd(&bsum, -nH * (1.0f / N));
    }
    __syncthreads();
    if (tid == 0) atomicAdd(out, bsum);
}

// ---------------------------------------------------------------------------
extern "C" void kernel_launch(void* const* d_in, const int* in_sizes, int n_in,
                              void* d_out, int out_size) {
    const float* emb    = (const float*)d_in[0];
    const int*   labels = (const int*)d_in[1];
    float*       out    = (float*)d_out;

    cudaFuncSetAttribute(gemm_kernel, cudaFuncAttributeMaxDynamicSharedMemorySize, GEMM_SMEM);

    prep_kernel<<<N / 8, 256>>>(emb, out);
    gemm_kernel<<<64 * 65 / 2, 256, GEMM_SMEM>>>(labels);   // 2080 upper-tri tiles
    row_kernel<<<N / 8, 256>>>(out);
}

// round 14
// speedup vs baseline: 3.7949x; 1.5938x over previous
#include <cuda_runtime.h>
#include <cuda_fp16.h>
#include <cstdint>

#define N 8192
#define D 512

static __device__ float g_cand[(size_t)N * 512];   // 16 MB: per row, 64 blocks x 8 packed
static __device__ float g_sqn[N];
static __device__ __half g_hi[(size_t)N * D];

// ---------------------------------------------------------------------------
// helpers
// ---------------------------------------------------------------------------
__device__ __forceinline__ uint32_t smem_u32(const void* p) {
    uint32_t a;
    asm("{ .reg .u64 t; cvta.to.shared.u64 t, %1; cvt.u32.u64 %0, t; }" : "=r"(a) : "l"(p));
    return a;
}
__device__ __forceinline__ uint32_t sw128(uint32_t b) { return b ^ ((b >> 3) & 0x70); }

__device__ __forceinline__ void cp16(uint32_t dst, const void* src) {
    asm volatile("cp.async.cg.shared.global [%0], [%1], 16;" :: "r"(dst), "l"(src));
}
#define CP_COMMIT() asm volatile("cp.async.commit_group;" ::: "memory")
#define CP_WAIT0()  asm volatile("cp.async.wait_group 0;" ::: "memory")
#define CP_WAIT1()  asm volatile("cp.async.wait_group 1;" ::: "memory")

__device__ __forceinline__ void ldsm_x4(uint32_t* r, uint32_t addr) {
    asm volatile("ldmatrix.sync.aligned.m8n8.x4.shared.b16 {%0,%1,%2,%3}, [%4];"
                 : "=r"(r[0]), "=r"(r[1]), "=r"(r[2]), "=r"(r[3]) : "r"(addr));
}
__device__ __forceinline__ void mma16816(float* d, const uint32_t* a, uint32_t b0, uint32_t b1) {
    asm volatile(
        "mma.sync.aligned.m16n8k16.row.col.f32.f16.f16.f32 "
        "{%0,%1,%2,%3}, {%4,%5,%6,%7}, {%8,%9}, {%0,%1,%2,%3};"
        : "+f"(d[0]), "+f"(d[1]), "+f"(d[2]), "+f"(d[3])
        : "r"(a[0]), "r"(a[1]), "r"(a[2]), "r"(a[3]), "r"(b0), "r"(b1));
}

// ---------------------------------------------------------------------------
// Kernel 1: sqnorms + fp32 -> fp16 (one warp per row), zero out
// ---------------------------------------------------------------------------
__global__ void prep_kernel(const float* __restrict__ emb, float* __restrict__ out) {
    if (blockIdx.x == 0 && threadIdx.x == 0) *out = 0.0f;
    int gw   = (blockIdx.x * blockDim.x + threadIdx.x) >> 5;
    int lane = threadIdx.x & 31;
    if (gw >= N) return;
    const float4* src = (const float4*)(emb + (size_t)gw * D);
    float s = 0.0f;
#pragma unroll
    for (int q = 0; q < 4; q++) {
        float4 v = src[lane + q * 32];
        s = fmaf(v.x, v.x, fmaf(v.y, v.y, fmaf(v.z, v.z, fmaf(v.w, v.w, s))));
        __half h[4];
        float f[4] = {v.x, v.y, v.z, v.w};
#pragma unroll
        for (int u = 0; u < 4; u++) h[u] = __float2half(f[u]);
        *(uint2*)(g_hi + (size_t)gw * D + lane * 4 + q * 128) = *(const uint2*)h;
    }
#pragma unroll
    for (int o = 16; o > 0; o >>= 1) s += __shfl_down_sync(0xffffffffu, s, o);
    if (lane == 0) g_sqn[gw] = s;
}

// ---------------------------------------------------------------------------
// Kernel 2: 128x128-tile symmetric distance GEMM via mma.sync fp16 (hi only).
// Single pass over K (8 chunks), 3-stage cp.async pipeline, upper-tri tiles.
// Epilogue: per-row top-8 candidates per block (label in 2 low bits),
// branchless FMNMX sorted insert; direct rows + mirrored columns.
// ---------------------------------------------------------------------------
#define STAGE_BYTES 32768          // A 16KB + B 16KB per K=64 chunk
#define NSTAGE 3
#define SST 129                    // transpose row stride: odd -> conflict-free both scans
#define LB_OFF 66560               // label arrays offset (128*129*4 = 66048)
#define GEMM_SMEM (NSTAGE * STAGE_BYTES)  // 98304 >= 66560 + 1024
#define NCHUNK 8                   // 1 pass x 8 k-chunks of 64

__device__ __forceinline__ void ins8(float loc[8], float v) {
    if (v < loc[7]) {
        loc[7] = v;
#pragma unroll
        for (int q = 7; q > 0; q--) {
            float a = loc[q - 1], b = loc[q];
            loc[q - 1] = fminf(a, b);
            loc[q]     = fmaxf(a, b);
        }
    }
}

__device__ __forceinline__ void load_chunk(int kc, uint32_t st, int i0, int j0, int tid) {
#pragma unroll
    for (int q = 0; q < 4; q++) {
        int idx = q * 256 + tid;
        int row = idx >> 3, seg = idx & 7;
        cp16(st + sw128(row * 128 + seg * 16),
             g_hi + (size_t)(i0 + row) * D + kc * 64 + seg * 8);
    }
#pragma unroll
    for (int q = 0; q < 4; q++) {
        int idx = q * 256 + tid;
        int row = idx >> 3, seg = idx & 7;
        cp16(st + 16384 + sw128(row * 128 + seg * 16),
             g_hi + (size_t)(j0 + row) * D + kc * 64 + seg * 8);
    }
    CP_COMMIT();
}

__global__ __launch_bounds__(256, 2) void gemm_kernel(const int* __restrict__ labels) {
    extern __shared__ __align__(1024) uint8_t dsm[];
    const int tid  = threadIdx.x;
    const int wid  = tid >> 5;
    const int lane = tid & 31;

    // upper-triangle tile decode (64x64 grid of 128-tiles)
    int t = blockIdx.x, bi = 0, rem = 64;
    while (t >= rem) { t -= rem; bi++; rem--; }
    const int bj = bi + t;
    const int i0 = bi * 128, j0 = bj * 128;

    const uint32_t dsm_b = smem_u32(dsm);
    const int wm = (wid >> 2) * 64;   // warp m-offset (0/64)
    const int wn = (wid & 3) * 32;    // warp n-offset (0/32/64/96)

    float acc[4][4][4];
#pragma unroll
    for (int a = 0; a < 4; a++)
#pragma unroll
        for (int b = 0; b < 4; b++)
#pragma unroll
            for (int k = 0; k < 4; k++) acc[a][b][k] = 0.0f;

    load_chunk(0, dsm_b, i0, j0, tid);
    load_chunk(1, dsm_b + STAGE_BYTES, i0, j0, tid);

    const uint32_t lrow = lane & 15, lhalf = (lane >> 4) * 16;
    int slot = 0;
    for (int c = 0; c < NCHUNK; c++) {
        if (c + 1 < NCHUNK) CP_WAIT1(); else CP_WAIT0();
        __syncthreads();
        if (c + 2 < NCHUNK) {
            int ns = slot + 2; if (ns >= NSTAGE) ns -= NSTAGE;
            load_chunk(c + 2, dsm_b + ns * STAGE_BYTES, i0, j0, tid);
        }
        const uint32_t stA = dsm_b + slot * STAGE_BYTES;
        const uint32_t stB = stA + 16384;
#pragma unroll
        for (int kk = 0; kk < 4; kk++) {
            uint32_t afr[4][4], bfr[2][4];
#pragma unroll
            for (int mf = 0; mf < 4; mf++)
                ldsm_x4(afr[mf], stA + sw128((wm + mf * 16 + lrow) * 128 + kk * 32 + lhalf));
#pragma unroll
            for (int g = 0; g < 2; g++)
                ldsm_x4(bfr[g], stB + sw128((wn + g * 16 + lrow) * 128 + kk * 32 + lhalf));
#pragma unroll
            for (int mf = 0; mf < 4; mf++)
#pragma unroll
                for (int nf = 0; nf < 4; nf++)
                    mma16816(acc[mf][nf], afr[mf],
                             bfr[nf >> 1][nf & 1], bfr[nf >> 1][(nf & 1) + 2]);
        }
        if (++slot == NSTAGE) slot = 0;
    }
    __syncthreads();   // everyone done reading stages before smem reuse

    // ---- epilogue: distances into smem tile d[r][c], plus label arrays
    float* smemf = (float*)dsm;
    uint32_t* lbA = (uint32_t*)(dsm + LB_OFF);        // labels[i0 + r]
    uint32_t* lbB = lbA + 128;                        // labels[j0 + c]
    if (tid < 128) lbA[tid] = (uint32_t)labels[i0 + tid];
    else           lbB[tid - 128] = (uint32_t)labels[j0 + tid - 128];

    const int qr = lane >> 2, qc = (lane & 3) * 2;
#pragma unroll
    for (int mf = 0; mf < 4; mf++) {
        const int r0 = wm + mf * 16 + qr;
        const float si0 = g_sqn[i0 + r0], si1 = g_sqn[i0 + r0 + 8];
#pragma unroll
        for (int nf = 0; nf < 4; nf++) {
            const int c0 = wn + nf * 8 + qc;
            const float sj0 = g_sqn[j0 + c0], sj1 = g_sqn[j0 + c0 + 1];
            const float* p = acc[mf][nf];
            float v00 = si0 + sj0 - 2.0f * p[0];
            float v01 = si0 + sj1 - 2.0f * p[1];
            float v10 = si1 + sj0 - 2.0f * p[2];
            float v11 = si1 + sj1 - 2.0f * p[3];
            if (i0 + r0     == j0 + c0)     v00 += 10000000000.0f;
            if (i0 + r0     == j0 + c0 + 1) v01 += 10000000000.0f;
            if (i0 + r0 + 8 == j0 + c0)     v10 += 10000000000.0f;
            if (i0 + r0 + 8 == j0 + c0 + 1) v11 += 10000000000.0f;
            smemf[r0 * SST + c0]           = v00;
            smemf[r0 * SST + c0 + 1]       = v01;
            smemf[(r0 + 8) * SST + c0]     = v10;
            smemf[(r0 + 8) * SST + c0 + 1] = v11;
        }
    }
    __syncthreads();

    const float INF = __int_as_float(0x7f800000);
    if (tid < 128) {
        // row scan: row i0+tid, candidates over cols j0..j0+127, pack label of col
        const int r = tid;
        float top[8];
#pragma unroll
        for (int q = 0; q < 8; q++) top[q] = INF;
        const float* base = smemf + r * SST;
#pragma unroll 4
        for (int c = 0; c < 128; c++) {
            uint32_t b = (__float_as_uint(base[c]) & ~3u) | lbB[c];
            ins8(top, __uint_as_float(b));
        }
        float4* dst = (float4*)(g_cand + (size_t)(i0 + r) * 512 + bj * 8);
        dst[0] = *(const float4*)&top[0];
        dst[1] = *(const float4*)&top[4];
    } else if (i0 != j0) {
        // col scan: row j0+(tid-128), candidates over rows i0..i0+127
        const int c = tid - 128;
        float top[8];
#pragma unroll
        for (int q = 0; q < 8; q++) top[q] = INF;
#pragma unroll 4
        for (int u = 0; u < 128; u++) {
            uint32_t b = (__float_as_uint(smemf[u * SST + c]) & ~3u) | lbA[u];
            ins8(top, __uint_as_float(b));
        }
        float4* dst = (float4*)(g_cand + (size_t)(j0 + c) * 512 + bi * 8);
        dst[0] = *(const float4*)&top[0];
        dst[1] = *(const float4*)&top[4];
    }
}

// ---------------------------------------------------------------------------
// Kernel 3: warp-per-row over 512 candidates: top-15 + thresholded
// softmax*mask + entropy. Labels packed in 2 low bits of each candidate.
// ---------------------------------------------------------------------------
__device__ __forceinline__ void ins15(float loc[15], float v) {
    if (v < loc[14]) {
        loc[14] = v;
#pragma unroll
        for (int q = 14; q > 0; q--) {
            if (loc[q] < loc[q - 1]) { float tt = loc[q - 1]; loc[q - 1] = loc[q]; loc[q] = tt; }
        }
    }
}

__global__ __launch_bounds__(256) void row_kernel(float* __restrict__ out) {
    const int tid  = threadIdx.x;
    const int wid  = tid >> 5;
    const int lane = tid & 31;
    const int row  = blockIdx.x * 8 + wid;

    __shared__ float bsum;
    if (tid == 0) bsum = 0.0f;
    __syncthreads();

    const float4* cr = (const float4*)(g_cand + (size_t)row * 512);
    const float INF = __int_as_float(0x7f800000);

    // phase 1: per-lane top-15 over 16 candidates + cache in regs
    float cv[16];
    float loc[15];
#pragma unroll
    for (int q = 0; q < 15; q++) loc[q] = INF;
#pragma unroll
    for (int k = 0; k < 4; k++) {
        float4 v = cr[lane + k * 32];
        cv[k * 4 + 0] = v.x; cv[k * 4 + 1] = v.y; cv[k * 4 + 2] = v.z; cv[k * 4 + 3] = v.w;
        ins15(loc, v.x); ins15(loc, v.y); ins15(loc, v.z); ins15(loc, v.w);
    }

    // phase 2: 15-round warp merge
    float dmin = 0.0f, kth = 0.0f;
#pragma unroll
    for (int r = 0; r < 15; r++) {
        float h = loc[0];
        float m = h;
#pragma unroll
        for (int o = 16; o > 0; o >>= 1) m = fminf(m, __shfl_xor_sync(0xffffffffu, m, o));
        unsigned ball = __ballot_sync(0xffffffffu, h == m);
        int winner = __ffs(ball) - 1;
        if (lane == winner) {
#pragma unroll
            for (int q = 0; q < 14; q++) loc[q] = loc[q + 1];
            loc[14] = INF;
        }
        if (r == 0)  dmin = m;
        if (r == 14) kth  = m;
    }

    // phase 3: thresholded accumulation over register-cached candidates
    const float thresh = dmin + 25.0f;
    const float C = __expf(dmin - kth);
    float Z = 0.f, S = 0.f, s0 = 0.f, s1 = 0.f, s2 = 0.f;
#pragma unroll
    for (int u = 0; u < 16; u++) {
        float d = cv[u];
        if (d < thresh) {
            float e  = __expf(dmin - d);
            float tt = __fdividef(e * e, e + C);   // e * sigmoid(kth-d)
            Z += e; S += tt;
            int lb = __float_as_uint(d) & 3u;
            s0 += (lb == 0) ? tt : 0.f;
            s1 += (lb == 1) ? tt : 0.f;
            s2 += (lb == 2) ? tt : 0.f;
        }
    }
#pragma unroll
    for (int o = 16; o > 0; o >>= 1) {
        Z  += __shfl_down_sync(0xffffffffu, Z,  o);
        S  += __shfl_down_sync(0xffffffffu, S,  o);
        s0 += __shfl_down_sync(0xffffffffu, s0, o);
        s1 += __shfl_down_sync(0xffffffffu, s1, o);
        s2 += __shfl_down_sync(0xffffffffu, s2, o);
    }
    if (lane == 0) {
        float denom = S + 1e-8f * Z;
        float p0 = s0 / denom, p1 = s1 / denom, p2 = s2 / denom;
        float H = -(p0 * logf(p0 + 1e-8f) + p1 * logf(p1 + 1e-8f) + p2 * logf(p2 + 1e-8f));
        float nH = H / (logf(3.0f) + 1e-8f);
        atomicAdd(&bsum, -nH * (1.0f / N));
    }
    __syncthreads();
    if (tid == 0) atomicAdd(out, bsum);
}

// ---------------------------------------------------------------------------
extern "C" void kernel_launch(void* const* d_in, const int* in_sizes, int n_in,
                              void* d_out, int out_size) {
    const float* emb    = (const float*)d_in[0];
    const int*   labels = (const int*)d_in[1];
    float*       out    = (float*)d_out;

    cudaFuncSetAttribute(gemm_kernel, cudaFuncAttributeMaxDynamicSharedMemorySize, GEMM_SMEM);

    prep_kernel<<<N / 8, 256>>>(emb, out);
    gemm_kernel<<<64 * 65 / 2, 256, GEMM_SMEM>>>(labels);   // 2080 upper-tri tiles
    row_kernel<<<N / 8, 256>>>(out);
}

// round 16
// speedup vs baseline: 4.0195x; 1.0592x over previous
#include <cuda_runtime.h>
#include <cuda_fp16.h>
#include <cstdint>

#define N 8192
#define D 512

static __device__ float g_cand[(size_t)N * 512];   // 16 MB: per row, 64 blocks x 8 packed
static __device__ float g_sqn[N];
static __device__ __half g_hi[(size_t)N * D];

// ---------------------------------------------------------------------------
// helpers
// ---------------------------------------------------------------------------
__device__ __forceinline__ uint32_t smem_u32(const void* p) {
    uint32_t a;
    asm("{ .reg .u64 t; cvta.to.shared.u64 t, %1; cvt.u32.u64 %0, t; }" : "=r"(a) : "l"(p));
    return a;
}
__device__ __forceinline__ uint32_t sw128(uint32_t b) { return b ^ ((b >> 3) & 0x70); }

__device__ __forceinline__ void cp16(uint32_t dst, const void* src) {
    asm volatile("cp.async.cg.shared.global [%0], [%1], 16;" :: "r"(dst), "l"(src));
}
#define CP_COMMIT() asm volatile("cp.async.commit_group;" ::: "memory")
#define CP_WAIT0()  asm volatile("cp.async.wait_group 0;" ::: "memory")
#define CP_WAIT1()  asm volatile("cp.async.wait_group 1;" ::: "memory")

__device__ __forceinline__ void ldsm_x4(uint32_t* r, uint32_t addr) {
    asm volatile("ldmatrix.sync.aligned.m8n8.x4.shared.b16 {%0,%1,%2,%3}, [%4];"
                 : "=r"(r[0]), "=r"(r[1]), "=r"(r[2]), "=r"(r[3]) : "r"(addr));
}
__device__ __forceinline__ void mma16816(float* d, const uint32_t* a, uint32_t b0, uint32_t b1) {
    asm volatile(
        "mma.sync.aligned.m16n8k16.row.col.f32.f16.f16.f32 "
        "{%0,%1,%2,%3}, {%4,%5,%6,%7}, {%8,%9}, {%0,%1,%2,%3};"
        : "+f"(d[0]), "+f"(d[1]), "+f"(d[2]), "+f"(d[3])
        : "r"(a[0]), "r"(a[1]), "r"(a[2]), "r"(a[3]), "r"(b0), "r"(b1));
}

// ---------------------------------------------------------------------------
// Kernel 1: sqnorms + fp32 -> fp16 (one warp per row), zero out
// ---------------------------------------------------------------------------
__global__ void prep_kernel(const float* __restrict__ emb, float* __restrict__ out) {
    if (blockIdx.x == 0 && threadIdx.x == 0) *out = 0.0f;
    int gw   = (blockIdx.x * blockDim.x + threadIdx.x) >> 5;
    int lane = threadIdx.x & 31;
    if (gw >= N) return;
    const float4* src = (const float4*)(emb + (size_t)gw * D);
    float s = 0.0f;
#pragma unroll
    for (int q = 0; q < 4; q++) {
        float4 v = src[lane + q * 32];
        s = fmaf(v.x, v.x, fmaf(v.y, v.y, fmaf(v.z, v.z, fmaf(v.w, v.w, s))));
        __half h[4];
        float f[4] = {v.x, v.y, v.z, v.w};
#pragma unroll
        for (int u = 0; u < 4; u++) h[u] = __float2half(f[u]);
        *(uint2*)(g_hi + (size_t)gw * D + lane * 4 + q * 128) = *(const uint2*)h;
    }
#pragma unroll
    for (int o = 16; o > 0; o >>= 1) s += __shfl_down_sync(0xffffffffu, s, o);
    if (lane == 0) g_sqn[gw] = s;
}

// ---------------------------------------------------------------------------
// Kernel 2: 128x128-tile symmetric distance GEMM via mma.sync fp16 (hi only).
// Single pass over K (8 chunks), 3-stage cp.async pipeline, upper-tri tiles.
// Epilogue: per-row/col mins tracked from registers (smem atomicMin), then
// threshold-gated top-8 scans (label in 2 low bits); mirror via col scans.
// ---------------------------------------------------------------------------
#define STAGE_BYTES 32768          // A 16KB + B 16KB per K=64 chunk
#define NSTAGE 3
#define SST 129                    // transpose row stride: odd -> conflict-free both scans
#define LB_OFF 66560               // label arrays (1KB) then rmin/cmin (1KB)
#define MIN_OFF (LB_OFF + 1024)
#define GEMM_SMEM (NSTAGE * STAGE_BYTES)  // 98304 >= 68608
#define NCHUNK 8                   // 1 pass x 8 k-chunks of 64

__device__ __forceinline__ void ins8(float loc[8], float v) {
    loc[7] = fminf(loc[7], v);
#pragma unroll
    for (int q = 7; q > 0; q--) {
        float a = loc[q - 1], b = loc[q];
        loc[q - 1] = fminf(a, b);
        loc[q]     = fmaxf(a, b);
    }
}

__device__ __forceinline__ void load_chunk(int kc, uint32_t st, int i0, int j0, int tid) {
#pragma unroll
    for (int q = 0; q < 4; q++) {
        int idx = q * 256 + tid;
        int row = idx >> 3, seg = idx & 7;
        cp16(st + sw128(row * 128 + seg * 16),
             g_hi + (size_t)(i0 + row) * D + kc * 64 + seg * 8);
    }
#pragma unroll
    for (int q = 0; q < 4; q++) {
        int idx = q * 256 + tid;
        int row = idx >> 3, seg = idx & 7;
        cp16(st + 16384 + sw128(row * 128 + seg * 16),
             g_hi + (size_t)(j0 + row) * D + kc * 64 + seg * 8);
    }
    CP_COMMIT();
}

__global__ __launch_bounds__(256, 2) void gemm_kernel(const int* __restrict__ labels) {
    extern __shared__ __align__(1024) uint8_t dsm[];
    const int tid  = threadIdx.x;
    const int wid  = tid >> 5;
    const int lane = tid & 31;

    // upper-triangle tile decode (64x64 grid of 128-tiles)
    int t = blockIdx.x, bi = 0, rem = 64;
    while (t >= rem) { t -= rem; bi++; rem--; }
    const int bj = bi + t;
    const int i0 = bi * 128, j0 = bj * 128;

    const uint32_t dsm_b = smem_u32(dsm);
    const int wm = (wid >> 2) * 64;   // warp m-offset (0/64)
    const int wn = (wid & 3) * 32;    // warp n-offset (0/32/64/96)

    float acc[4][4][4];
#pragma unroll
    for (int a = 0; a < 4; a++)
#pragma unroll
        for (int b = 0; b < 4; b++)
#pragma unroll
            for (int k = 0; k < 4; k++) acc[a][b][k] = 0.0f;

    load_chunk(0, dsm_b, i0, j0, tid);
    load_chunk(1, dsm_b + STAGE_BYTES, i0, j0, tid);

    const uint32_t lrow = lane & 15, lhalf = (lane >> 4) * 16;
    int slot = 0;
    for (int c = 0; c < NCHUNK; c++) {
        if (c + 1 < NCHUNK) CP_WAIT1(); else CP_WAIT0();
        __syncthreads();
        if (c + 2 < NCHUNK) {
            int ns = slot + 2; if (ns >= NSTAGE) ns -= NSTAGE;
            load_chunk(c + 2, dsm_b + ns * STAGE_BYTES, i0, j0, tid);
        }
        const uint32_t stA = dsm_b + slot * STAGE_BYTES;
        const uint32_t stB = stA + 16384;
#pragma unroll
        for (int kk = 0; kk < 4; kk++) {
            uint32_t afr[4][4], bfr[2][4];
#pragma unroll
            for (int mf = 0; mf < 4; mf++)
                ldsm_x4(afr[mf], stA + sw128((wm + mf * 16 + lrow) * 128 + kk * 32 + lhalf));
#pragma unroll
            for (int g = 0; g < 2; g++)
                ldsm_x4(bfr[g], stB + sw128((wn + g * 16 + lrow) * 128 + kk * 32 + lhalf));
#pragma unroll
            for (int mf = 0; mf < 4; mf++)
#pragma unroll
                for (int nf = 0; nf < 4; nf++)
                    mma16816(acc[mf][nf], afr[mf],
                             bfr[nf >> 1][nf & 1], bfr[nf >> 1][(nf & 1) + 2]);
        }
        if (++slot == NSTAGE) slot = 0;
    }
    __syncthreads();   // everyone done reading stages before smem reuse

    // ---- epilogue: distances into smem tile + per-row/col mins + labels
    float* smemf = (float*)dsm;
    uint32_t* lbA = (uint32_t*)(dsm + LB_OFF);        // labels[i0 + r]
    uint32_t* lbB = lbA + 128;                        // labels[j0 + c]
    int* rmin = (int*)(dsm + MIN_OFF);                // per-row min (as int bits)
    int* cmin = rmin + 128;                           // per-col min
    if (tid < 128) { lbA[tid] = (uint32_t)labels[i0 + tid]; rmin[tid] = 0x7f7fffff; }
    else           { lbB[tid - 128] = (uint32_t)labels[j0 + tid - 128]; cmin[tid - 128] = 0x7f7fffff; }
    __syncthreads();

    const int qr = lane >> 2, qc = (lane & 3) * 2;
    float colm[4][2];   // per nf, per col-in-pair min (across mf)
#pragma unroll
    for (int nf = 0; nf < 4; nf++) { colm[nf][0] = 1e30f; colm[nf][1] = 1e30f; }
#pragma unroll
    for (int mf = 0; mf < 4; mf++) {
        const int r0 = wm + mf * 16 + qr;
        const float si0 = g_sqn[i0 + r0], si1 = g_sqn[i0 + r0 + 8];
        float rowm0 = 1e30f, rowm1 = 1e30f;
#pragma unroll
        for (int nf = 0; nf < 4; nf++) {
            const int c0 = wn + nf * 8 + qc;
            const float sj0 = g_sqn[j0 + c0], sj1 = g_sqn[j0 + c0 + 1];
            const float* p = acc[mf][nf];
            float v00 = si0 + sj0 - 2.0f * p[0];
            float v01 = si0 + sj1 - 2.0f * p[1];
            float v10 = si1 + sj0 - 2.0f * p[2];
            float v11 = si1 + sj1 - 2.0f * p[3];
            if (i0 + r0     == j0 + c0)     v00 += 10000000000.0f;
            if (i0 + r0     == j0 + c0 + 1) v01 += 10000000000.0f;
            if (i0 + r0 + 8 == j0 + c0)     v10 += 10000000000.0f;
            if (i0 + r0 + 8 == j0 + c0 + 1) v11 += 10000000000.0f;
            smemf[r0 * SST + c0]           = v00;
            smemf[r0 * SST + c0 + 1]       = v01;
            smemf[(r0 + 8) * SST + c0]     = v10;
            smemf[(r0 + 8) * SST + c0 + 1] = v11;
            rowm0 = fminf(rowm0, fminf(v00, v01));
            rowm1 = fminf(rowm1, fminf(v10, v11));
            colm[nf][0] = fminf(colm[nf][0], fminf(v00, v10));
            colm[nf][1] = fminf(colm[nf][1], fminf(v01, v11));
        }
        atomicMin(&rmin[r0],     __float_as_int(rowm0));
        atomicMin(&rmin[r0 + 8], __float_as_int(rowm1));
    }
#pragma unroll
    for (int nf = 0; nf < 4; nf++) {
        const int c0 = wn + nf * 8 + qc;
        atomicMin(&cmin[c0],     __float_as_int(colm[nf][0]));
        atomicMin(&cmin[c0 + 1], __float_as_int(colm[nf][1]));
    }
    __syncthreads();

    const float INF = __int_as_float(0x7f800000);
    if (tid < 128) {
        // row scan: row i0+tid over cols, gated by rowmin+25
        const int r = tid;
        const float lim = __int_as_float(rmin[r]) + 25.0f;
        float top[8];
#pragma unroll
        for (int q = 0; q < 8; q++) top[q] = INF;
        const float* base = smemf + r * SST;
#pragma unroll 4
        for (int c = 0; c < 128; c++) {
            float v = base[c];
            if (v < lim) {
                uint32_t b = (__float_as_uint(v) & ~3u) | lbB[c];
                ins8(top, __uint_as_float(b));
            }
        }
        float4* dst = (float4*)(g_cand + (size_t)(i0 + r) * 512 + bj * 8);
        dst[0] = *(const float4*)&top[0];
        dst[1] = *(const float4*)&top[4];
    } else if (i0 != j0) {
        // col scan: row j0+(tid-128) over rows, gated by colmin+25
        const int c = tid - 128;
        const float lim = __int_as_float(cmin[c]) + 25.0f;
        float top[8];
#pragma unroll
        for (int q = 0; q < 8; q++) top[q] = INF;
#pragma unroll 4
        for (int u = 0; u < 128; u++) {
            float v = smemf[u * SST + c];
            if (v < lim) {
                uint32_t b = (__float_as_uint(v) & ~3u) | lbA[u];
                ins8(top, __uint_as_float(b));
            }
        }
        float4* dst = (float4*)(g_cand + (size_t)(j0 + c) * 512 + bi * 8);
        dst[0] = *(const float4*)&top[0];
        dst[1] = *(const float4*)&top[4];
    }
}

// ---------------------------------------------------------------------------
// Kernel 3: warp-per-row over 512 candidates: top-15 + thresholded
// softmax*mask + entropy. Labels packed in 2 low bits of each candidate.
// ---------------------------------------------------------------------------
__device__ __forceinline__ void ins15(float loc[15], float v) {
    if (v < loc[14]) {
        loc[14] = v;
#pragma unroll
        for (int q = 14; q > 0; q--) {
            if (loc[q] < loc[q - 1]) { float tt = loc[q - 1]; loc[q - 1] = loc[q]; loc[q] = tt; }
        }
    }
}

__global__ __launch_bounds__(256) void row_kernel(float* __restrict__ out) {
    const int tid  = threadIdx.x;
    const int wid  = tid >> 5;
    const int lane = tid & 31;
    const int row  = blockIdx.x * 8 + wid;

    __shared__ float bsum;
    if (tid == 0) bsum = 0.0f;
    __syncthreads();

    const float4* cr = (const float4*)(g_cand + (size_t)row * 512);
    const float INF = __int_as_float(0x7f800000);

    // phase 1: per-lane top-15 over 16 candidates + cache in regs
    float cv[16];
    float loc[15];
#pragma unroll
    for (int q = 0; q < 15; q++) loc[q] = INF;
#pragma unroll
    for (int k = 0; k < 4; k++) {
        float4 v = cr[lane + k * 32];
        cv[k * 4 + 0] = v.x; cv[k * 4 + 1] = v.y; cv[k * 4 + 2] = v.z; cv[k * 4 + 3] = v.w;
        ins15(loc, v.x); ins15(loc, v.y); ins15(loc, v.z); ins15(loc, v.w);
    }

    // phase 2: 15-round warp merge
    float dmin = 0.0f, kth = 0.0f;
#pragma unroll
    for (int r = 0; r < 15; r++) {
        float h = loc[0];
        float m = h;
#pragma unroll
        for (int o = 16; o > 0; o >>= 1) m = fminf(m, __shfl_xor_sync(0xffffffffu, m, o));
        unsigned ball = __ballot_sync(0xffffffffu, h == m);
        int winner = __ffs(ball) - 1;
        if (lane == winner) {
#pragma unroll
            for (int q = 0; q < 14; q++) loc[q] = loc[q + 1];
            loc[14] = INF;
        }
        if (r == 0)  dmin = m;
        if (r == 14) kth  = m;
    }

    // phase 3: thresholded accumulation over register-cached candidates
    const float thresh = dmin + 25.0f;
    const float C = __expf(dmin - kth);
    float Z = 0.f, S = 0.f, s0 = 0.f, s1 = 0.f, s2 = 0.f;
#pragma unroll
    for (int u = 0; u < 16; u++) {
        float d = cv[u];
        if (d < thresh) {
            float e  = __expf(dmin - d);
            float tt = __fdividef(e * e, e + C);   // e * sigmoid(kth-d)
            Z += e; S += tt;
            int lb = __float_as_uint(d) & 3u;
            s0 += (lb == 0) ? tt : 0.f;
            s1 += (lb == 1) ? tt : 0.f;
            s2 += (lb == 2) ? tt : 0.f;
        }
    }
#pragma unroll
    for (int o = 16; o > 0; o >>= 1) {
        Z  += __shfl_down_sync(0xffffffffu, Z,  o);
        S  += __shfl_down_sync(0xffffffffu, S,  o);
        s0 += __shfl_down_sync(0xffffffffu, s0, o);
        s1 += __shfl_down_sync(0xffffffffu, s1, o);
        s2 += __shfl_down_sync(0xffffffffu, s2, o);
    }
    if (lane == 0) {
        float denom = S + 1e-8f * Z;
        float p0 = s0 / denom, p1 = s1 / denom, p2 = s2 / denom;
        float H = -(p0 * logf(p0 + 1e-8f) + p1 * logf(p1 + 1e-8f) + p2 * logf(p2 + 1e-8f));
        float nH = H / (logf(3.0f) + 1e-8f);
        atomicAdd(&bsum, -nH * (1.0f / N));
    }
    __syncthreads();
    if (tid == 0) atomicAdd(out, bsum);
}

// ---------------------------------------------------------------------------
extern "C" void kernel_launch(void* const* d_in, const int* in_sizes, int n_in,
                              void* d_out, int out_size) {
    const float* emb    = (const float*)d_in[0];
    const int*   labels = (const int*)d_in[1];
    float*       out    = (float*)d_out;

    cudaFuncSetAttribute(gemm_kernel, cudaFuncAttributeMaxDynamicSharedMemorySize, GEMM_SMEM);

    prep_kernel<<<N / 8, 256>>>(emb, out);
    gemm_kernel<<<64 * 65 / 2, 256, GEMM_SMEM>>>(labels);   // 2080 upper-tri tiles
    row_kernel<<<N / 8, 256>>>(out);
}

// round 17
// speedup vs baseline: 4.2785x; 1.0644x over previous
#include <cuda_runtime.h>
#include <cuda_fp16.h>
#include <cstdint>

#define N 8192
#define D 512

static __device__ float g_cand[(size_t)N * 512];   // 16 MB: per row, 64 blocks x 8 packed
static __device__ float g_sqn[N];
static __device__ __half g_hi[(size_t)N * D];

// ---------------------------------------------------------------------------
// helpers
// ---------------------------------------------------------------------------
__device__ __forceinline__ uint32_t smem_u32(const void* p) {
    uint32_t a;
    asm("{ .reg .u64 t; cvta.to.shared.u64 t, %1; cvt.u32.u64 %0, t; }" : "=r"(a) : "l"(p));
    return a;
}
__device__ __forceinline__ uint32_t sw128(uint32_t b) { return b ^ ((b >> 3) & 0x70); }

__device__ __forceinline__ void cp16(uint32_t dst, const void* src) {
    asm volatile("cp.async.cg.shared.global [%0], [%1], 16;" :: "r"(dst), "l"(src));
}
#define CP_COMMIT() asm volatile("cp.async.commit_group;" ::: "memory")
#define CP_WAIT0()  asm volatile("cp.async.wait_group 0;" ::: "memory")
#define CP_WAIT1()  asm volatile("cp.async.wait_group 1;" ::: "memory")

__device__ __forceinline__ void ldsm_x4(uint32_t* r, uint32_t addr) {
    asm volatile("ldmatrix.sync.aligned.m8n8.x4.shared.b16 {%0,%1,%2,%3}, [%4];"
                 : "=r"(r[0]), "=r"(r[1]), "=r"(r[2]), "=r"(r[3]) : "r"(addr));
}
__device__ __forceinline__ void mma16816(float* d, const uint32_t* a, uint32_t b0, uint32_t b1) {
    asm volatile(
        "mma.sync.aligned.m16n8k16.row.col.f32.f16.f16.f32 "
        "{%0,%1,%2,%3}, {%4,%5,%6,%7}, {%8,%9}, {%0,%1,%2,%3};"
        : "+f"(d[0]), "+f"(d[1]), "+f"(d[2]), "+f"(d[3])
        : "r"(a[0]), "r"(a[1]), "r"(a[2]), "r"(a[3]), "r"(b0), "r"(b1));
}

// ---------------------------------------------------------------------------
// Kernel 1: sqnorms + fp32 -> fp16 (one warp per row), zero out
// ---------------------------------------------------------------------------
__global__ void prep_kernel(const float* __restrict__ emb, float* __restrict__ out) {
    if (blockIdx.x == 0 && threadIdx.x == 0) *out = 0.0f;
    int gw   = (blockIdx.x * blockDim.x + threadIdx.x) >> 5;
    int lane = threadIdx.x & 31;
    if (gw >= N) return;
    const float4* src = (const float4*)(emb + (size_t)gw * D);
    float s = 0.0f;
#pragma unroll
    for (int q = 0; q < 4; q++) {
        float4 v = src[lane + q * 32];
        s = fmaf(v.x, v.x, fmaf(v.y, v.y, fmaf(v.z, v.z, fmaf(v.w, v.w, s))));
        __half h[4];
        float f[4] = {v.x, v.y, v.z, v.w};
#pragma unroll
        for (int u = 0; u < 4; u++) h[u] = __float2half(f[u]);
        *(uint2*)(g_hi + (size_t)gw * D + lane * 4 + q * 128) = *(const uint2*)h;
    }
#pragma unroll
    for (int o = 16; o > 0; o >>= 1) s += __shfl_down_sync(0xffffffffu, s, o);
    if (lane == 0) g_sqn[gw] = s;
}

// ---------------------------------------------------------------------------
// Kernel 2: 128x128-tile symmetric distance GEMM via mma.sync fp16 (hi only).
// Single pass over K (8 chunks), 3-stage cp.async pipeline, upper-tri tiles.
// Epilogue: distances stay in registers; per-row/col block-mins via smem
// atomicMin; survivors (v < min+25) pushed into compact per-row/col lists
// (atomicAdd, CAP=16); tiny sort per list. No tile store, no scans.
// ---------------------------------------------------------------------------
#define STAGE_BYTES 32768          // A 16KB + B 16KB per K=64 chunk
#define NSTAGE 3
#define GEMM_SMEM (NSTAGE * STAGE_BYTES)  // 98304
#define NCHUNK 8                   // 1 pass x 8 k-chunks of 64
#define CAP 16

__device__ __forceinline__ void ins8(float loc[8], float v) {
    loc[7] = fminf(loc[7], v);
#pragma unroll
    for (int q = 7; q > 0; q--) {
        float a = loc[q - 1], b = loc[q];
        loc[q - 1] = fminf(a, b);
        loc[q]     = fmaxf(a, b);
    }
}

__device__ __forceinline__ void pushc(int* cnt, float* buf, int idx, float v, uint32_t lb) {
    uint32_t b = (__float_as_uint(v) & ~3u) | lb;
    int k = atomicAdd(&cnt[idx], 1);
    if (k < CAP) buf[idx * CAP + k] = __uint_as_float(b);
}

__device__ __forceinline__ void load_chunk(int kc, uint32_t st, int i0, int j0, int tid) {
#pragma unroll
    for (int q = 0; q < 4; q++) {
        int idx = q * 256 + tid;
        int row = idx >> 3, seg = idx & 7;
        cp16(st + sw128(row * 128 + seg * 16),
             g_hi + (size_t)(i0 + row) * D + kc * 64 + seg * 8);
    }
#pragma unroll
    for (int q = 0; q < 4; q++) {
        int idx = q * 256 + tid;
        int row = idx >> 3, seg = idx & 7;
        cp16(st + 16384 + sw128(row * 128 + seg * 16),
             g_hi + (size_t)(j0 + row) * D + kc * 64 + seg * 8);
    }
    CP_COMMIT();
}

__global__ __launch_bounds__(256, 2) void gemm_kernel(const int* __restrict__ labels) {
    extern __shared__ __align__(1024) uint8_t dsm[];
    const int tid  = threadIdx.x;
    const int wid  = tid >> 5;
    const int lane = tid & 31;

    // upper-triangle tile decode (64x64 grid of 128-tiles)
    int t = blockIdx.x, bi = 0, rem = 64;
    while (t >= rem) { t -= rem; bi++; rem--; }
    const int bj = bi + t;
    const int i0 = bi * 128, j0 = bj * 128;

    const uint32_t dsm_b = smem_u32(dsm);
    const int wm = (wid >> 2) * 64;   // warp m-offset (0/64)
    const int wn = (wid & 3) * 32;    // warp n-offset (0/32/64/96)

    float acc[4][4][4];
#pragma unroll
    for (int a = 0; a < 4; a++)
#pragma unroll
        for (int b = 0; b < 4; b++)
#pragma unroll
            for (int k = 0; k < 4; k++) acc[a][b][k] = 0.0f;

    load_chunk(0, dsm_b, i0, j0, tid);
    load_chunk(1, dsm_b + STAGE_BYTES, i0, j0, tid);

    const uint32_t lrow = lane & 15, lhalf = (lane >> 4) * 16;
    int slot = 0;
    for (int c = 0; c < NCHUNK; c++) {
        if (c + 1 < NCHUNK) CP_WAIT1(); else CP_WAIT0();
        __syncthreads();
        if (c + 2 < NCHUNK) {
            int ns = slot + 2; if (ns >= NSTAGE) ns -= NSTAGE;
            load_chunk(c + 2, dsm_b + ns * STAGE_BYTES, i0, j0, tid);
        }
        const uint32_t stA = dsm_b + slot * STAGE_BYTES;
        const uint32_t stB = stA + 16384;
#pragma unroll
        for (int kk = 0; kk < 4; kk++) {
            uint32_t afr[4][4], bfr[2][4];
#pragma unroll
            for (int mf = 0; mf < 4; mf++)
                ldsm_x4(afr[mf], stA + sw128((wm + mf * 16 + lrow) * 128 + kk * 32 + lhalf));
#pragma unroll
            for (int g = 0; g < 2; g++)
                ldsm_x4(bfr[g], stB + sw128((wn + g * 16 + lrow) * 128 + kk * 32 + lhalf));
#pragma unroll
            for (int mf = 0; mf < 4; mf++)
#pragma unroll
                for (int nf = 0; nf < 4; nf++)
                    mma16816(acc[mf][nf], afr[mf],
                             bfr[nf >> 1][nf & 1], bfr[nf >> 1][(nf & 1) + 2]);
        }
        if (++slot == NSTAGE) slot = 0;
    }
    __syncthreads();   // stage smem free for epilogue reuse

    // ---- epilogue smem layout (overlays stage area)
    int*      rmin   = (int*)dsm;                 // [128]
    int*      cmin   = rmin + 128;                // [128]
    int*      rcnt   = cmin + 128;                // [128]
    int*      ccnt   = rcnt + 128;                // [128]
    uint32_t* lbA    = (uint32_t*)(ccnt + 128);   // [128] labels[i0+r]
    uint32_t* lbB    = lbA + 128;                 // [128] labels[j0+c]
    float*    rowbuf = (float*)(lbB + 128);       // [128*CAP]
    float*    colbuf = rowbuf + 128 * CAP;        // [128*CAP]

    if (tid < 128) { rmin[tid] = 0x7f7fffff; rcnt[tid] = 0; lbA[tid] = (uint32_t)labels[i0 + tid]; }
    else { cmin[tid - 128] = 0x7f7fffff; ccnt[tid - 128] = 0; lbB[tid - 128] = (uint32_t)labels[j0 + tid - 128]; }
    __syncthreads();

    // Phase A: distances into acc (in place) + block row/col mins
    const int qr = lane >> 2, qc = (lane & 3) * 2;
    float colm[4][2];
#pragma unroll
    for (int nf = 0; nf < 4; nf++) { colm[nf][0] = 1e30f; colm[nf][1] = 1e30f; }
#pragma unroll
    for (int mf = 0; mf < 4; mf++) {
        const int r0 = wm + mf * 16 + qr;
        const float si0 = g_sqn[i0 + r0], si1 = g_sqn[i0 + r0 + 8];
        float rowm0 = 1e30f, rowm1 = 1e30f;
#pragma unroll
        for (int nf = 0; nf < 4; nf++) {
            const int c0 = wn + nf * 8 + qc;
            const float sj0 = g_sqn[j0 + c0], sj1 = g_sqn[j0 + c0 + 1];
            float* p = acc[mf][nf];
            float v00 = si0 + sj0 - 2.0f * p[0];
            float v01 = si0 + sj1 - 2.0f * p[1];
            float v10 = si1 + sj0 - 2.0f * p[2];
            float v11 = si1 + sj1 - 2.0f * p[3];
            if (i0 + r0     == j0 + c0)     v00 += 10000000000.0f;
            if (i0 + r0     == j0 + c0 + 1) v01 += 10000000000.0f;
            if (i0 + r0 + 8 == j0 + c0)     v10 += 10000000000.0f;
            if (i0 + r0 + 8 == j0 + c0 + 1) v11 += 10000000000.0f;
            p[0] = v00; p[1] = v01; p[2] = v10; p[3] = v11;
            rowm0 = fminf(rowm0, fminf(v00, v01));
            rowm1 = fminf(rowm1, fminf(v10, v11));
            colm[nf][0] = fminf(colm[nf][0], fminf(v00, v10));
            colm[nf][1] = fminf(colm[nf][1], fminf(v01, v11));
        }
        atomicMin(&rmin[r0],     __float_as_int(rowm0));
        atomicMin(&rmin[r0 + 8], __float_as_int(rowm1));
    }
#pragma unroll
    for (int nf = 0; nf < 4; nf++) {
        const int c0 = wn + nf * 8 + qc;
        atomicMin(&cmin[c0],     __float_as_int(colm[nf][0]));
        atomicMin(&cmin[c0 + 1], __float_as_int(colm[nf][1]));
    }
    __syncthreads();

    // Phase B: gate register values against limits; push survivors
    const bool offd = (i0 != j0);
#pragma unroll
    for (int mf = 0; mf < 4; mf++) {
        const int r0 = wm + mf * 16 + qr;
        const float rlA = __int_as_float(rmin[r0]) + 25.0f;
        const float rlB = __int_as_float(rmin[r0 + 8]) + 25.0f;
        const uint32_t la0 = lbA[r0], la1 = lbA[r0 + 8];
#pragma unroll
        for (int nf = 0; nf < 4; nf++) {
            const int c0 = wn + nf * 8 + qc;
            const float clA = __int_as_float(cmin[c0]) + 25.0f;
            const float clB = __int_as_float(cmin[c0 + 1]) + 25.0f;
            const uint32_t lb0 = lbB[c0], lb1 = lbB[c0 + 1];
            const float* p = acc[mf][nf];
            if (p[0] < rlA) pushc(rcnt, rowbuf, r0,     p[0], lb0);
            if (p[1] < rlA) pushc(rcnt, rowbuf, r0,     p[1], lb1);
            if (p[2] < rlB) pushc(rcnt, rowbuf, r0 + 8, p[2], lb0);
            if (p[3] < rlB) pushc(rcnt, rowbuf, r0 + 8, p[3], lb1);
            if (offd) {
                if (p[0] < clA) pushc(ccnt, colbuf, c0,     p[0], la0);
                if (p[2] < clA) pushc(ccnt, colbuf, c0,     p[2], la1);
                if (p[1] < clB) pushc(ccnt, colbuf, c0 + 1, p[1], la0);
                if (p[3] < clB) pushc(ccnt, colbuf, c0 + 1, p[3], la1);
            }
        }
    }
    __syncthreads();

    // Phase C: sort each compact list, write top-8 candidates
    const float INF = __int_as_float(0x7f800000);
    if (tid < 128) {
        const int r = tid;
        int cnt = rcnt[r]; if (cnt > CAP) cnt = CAP;
        float top[8];
#pragma unroll
        for (int q = 0; q < 8; q++) top[q] = INF;
        for (int k = 0; k < cnt; k++) ins8(top, rowbuf[r * CAP + k]);
        float4* dst = (float4*)(g_cand + (size_t)(i0 + r) * 512 + bj * 8);
        dst[0] = *(const float4*)&top[0];
        dst[1] = *(const float4*)&top[4];
    } else if (offd) {
        const int c = tid - 128;
        int cnt = ccnt[c]; if (cnt > CAP) cnt = CAP;
        float top[8];
#pragma unroll
        for (int q = 0; q < 8; q++) top[q] = INF;
        for (int k = 0; k < cnt; k++) ins8(top, colbuf[c * CAP + k]);
        float4* dst = (float4*)(g_cand + (size_t)(j0 + c) * 512 + bi * 8);
        dst[0] = *(const float4*)&top[0];
        dst[1] = *(const float4*)&top[4];
    }
}

// ---------------------------------------------------------------------------
// Kernel 3: warp-per-row over 512 candidates: top-15 + thresholded
// softmax*mask + entropy. Labels packed in 2 low bits of each candidate.
// ---------------------------------------------------------------------------
__device__ __forceinline__ void ins15(float loc[15], float v) {
    if (v < loc[14]) {
        loc[14] = v;
#pragma unroll
        for (int q = 14; q > 0; q--) {
            if (loc[q] < loc[q - 1]) { float tt = loc[q - 1]; loc[q - 1] = loc[q]; loc[q] = tt; }
        }
    }
}

__global__ __launch_bounds__(256) void row_kernel(float* __restrict__ out) {
    const int tid  = threadIdx.x;
    const int wid  = tid >> 5;
    const int lane = tid & 31;
    const int row  = blockIdx.x * 8 + wid;

    __shared__ float bsum;
    if (tid == 0) bsum = 0.0f;
    __syncthreads();

    const float4* cr = (const float4*)(g_cand + (size_t)row * 512);
    const float INF = __int_as_float(0x7f800000);

    // phase 1: per-lane top-15 over 16 candidates + cache in regs
    float cv[16];
    float loc[15];
#pragma unroll
    for (int q = 0; q < 15; q++) loc[q] = INF;
#pragma unroll
    for (int k = 0; k < 4; k++) {
        float4 v = cr[lane + k * 32];
        cv[k * 4 + 0] = v.x; cv[k * 4 + 1] = v.y; cv[k * 4 + 2] = v.z; cv[k * 4 + 3] = v.w;
        ins15(loc, v.x); ins15(loc, v.y); ins15(loc, v.z); ins15(loc, v.w);
    }

    // phase 2: 15-round warp merge
    float dmin = 0.0f, kth = 0.0f;
#pragma unroll
    for (int r = 0; r < 15; r++) {
        float h = loc[0];
        float m = h;
#pragma unroll
        for (int o = 16; o > 0; o >>= 1) m = fminf(m, __shfl_xor_sync(0xffffffffu, m, o));
        unsigned ball = __ballot_sync(0xffffffffu, h == m);
        int winner = __ffs(ball) - 1;
        if (lane == winner) {
#pragma unroll
            for (int q = 0; q < 14; q++) loc[q] = loc[q + 1];
            loc[14] = INF;
        }
        if (r == 0)  dmin = m;
        if (r == 14) kth  = m;
    }

    // phase 3: thresholded accumulation over register-cached candidates
    const float thresh = dmin + 25.0f;
    const float C = __expf(dmin - kth);
    float Z = 0.f, S = 0.f, s0 = 0.f, s1 = 0.f, s2 = 0.f;
#pragma unroll
    for (int u = 0; u < 16; u++) {
        float d = cv[u];
        if (d < thresh) {
            float e  = __expf(dmin - d);
            float tt = __fdividef(e * e, e + C);   // e * sigmoid(kth-d)
            Z += e; S += tt;
            int lb = __float_as_uint(d) & 3u;
            s0 += (lb == 0) ? tt : 0.f;
            s1 += (lb == 1) ? tt : 0.f;
            s2 += (lb == 2) ? tt : 0.f;
        }
    }
#pragma unroll
    for (int o = 16; o > 0; o >>= 1) {
        Z  += __shfl_down_sync(0xffffffffu, Z,  o);
        S  += __shfl_down_sync(0xffffffffu, S,  o);
        s0 += __shfl_down_sync(0xffffffffu, s0, o);
        s1 += __shfl_down_sync(0xffffffffu, s1, o);
        s2 += __shfl_down_sync(0xffffffffu, s2, o);
    }
    if (lane == 0) {
        float denom = S + 1e-8f * Z;
        float p0 = s0 / denom, p1 = s1 / denom, p2 = s2 / denom;
        float H = -(p0 * logf(p0 + 1e-8f) + p1 * logf(p1 + 1e-8f) + p2 * logf(p2 + 1e-8f));
        float nH = H / (logf(3.0f) + 1e-8f);
        atomicAdd(&bsum, -nH * (1.0f / N));
    }
    __syncthreads();
    if (tid == 0) atomicAdd(out, bsum);
}

// ---------------------------------------------------------------------------
extern "C" void kernel_launch(void* const* d_in, const int* in_sizes, int n_in,
                              void* d_out, int out_size) {
    const float* emb    = (const float*)d_in[0];
    const int*   labels = (const int*)d_in[1];
    float*       out    = (float*)d_out;

    cudaFuncSetAttribute(gemm_kernel, cudaFuncAttributeMaxDynamicSharedMemorySize, GEMM_SMEM);

    prep_kernel<<<N / 8, 256>>>(emb, out);
    gemm_kernel<<<64 * 65 / 2, 256, GEMM_SMEM>>>(labels);   // 2080 upper-tri tiles
    row_kernel<<<N / 8, 256>>>(out);
}